// round 1
// baseline (speedup 1.0000x reference)
#include <cuda_runtime.h>
#include <math.h>

#define Bb 2
#define Ss 2048
#define Dd 1024
#define Hh 16
#define HDIM 64
#define Mrows (Bb*Ss)   // 4096
#define QKVD (3*Dd)     // 3072

// Scratch (static device allocations are permitted)
__device__ float g_xn[(size_t)Mrows * Dd];          // 16 MB
__device__ float g_qkv[(size_t)Mrows * QKVD];       // 48 MB
__device__ float g_y[(size_t)Mrows * Dd];           // 16 MB
__device__ float g_cos[Ss * 32];
__device__ float g_sin[Ss * 32];

// ---------------------------------------------------------------------------
// RMSNorm: one block per row
// ---------------------------------------------------------------------------
__global__ void rmsnorm_kernel(const float* __restrict__ x,
                               const float* __restrict__ w) {
    const int row = blockIdx.x;
    const float* xr = x + (size_t)row * Dd;
    float ss = 0.f;
    for (int i = threadIdx.x; i < Dd; i += blockDim.x) {
        float v = xr[i];
        ss += v * v;
    }
    __shared__ float red[32];
    #pragma unroll
    for (int o = 16; o > 0; o >>= 1) ss += __shfl_xor_sync(0xffffffffu, ss, o);
    const int wid = threadIdx.x >> 5, lid = threadIdx.x & 31;
    if (lid == 0) red[wid] = ss;
    __syncthreads();
    if (wid == 0) {
        ss = (lid < (int)(blockDim.x >> 5)) ? red[lid] : 0.f;
        #pragma unroll
        for (int o = 16; o > 0; o >>= 1) ss += __shfl_xor_sync(0xffffffffu, ss, o);
        if (lid == 0) red[0] = ss;
    }
    __syncthreads();
    const float inv = rsqrtf(red[0] * (1.0f / Dd) + 1e-6f);
    float* out = g_xn + (size_t)row * Dd;
    for (int i = threadIdx.x; i < Dd; i += blockDim.x)
        out[i] = xr[i] * inv * w[i];
}

// ---------------------------------------------------------------------------
// RoPE cos/sin table (fp64 trig for accurate range reduction at t ~ 2048)
// ---------------------------------------------------------------------------
__global__ void rope_table_kernel() {
    const int t = blockIdx.x;
    const int i = threadIdx.x;  // 0..31
    double inv = pow(10000.0, -((double)(2 * i)) / 64.0);
    double a = (double)t * inv;
    g_cos[t * 32 + i] = (float)cos(a);
    g_sin[t * 32 + i] = (float)sin(a);
}

// ---------------------------------------------------------------------------
// RoPE apply (in-place on q and k inside g_qkv)
// idx bits: j[0:5) h[5:9) s[9:20) b[20]
// ---------------------------------------------------------------------------
__global__ void rope_kernel() {
    const int idx = blockIdx.x * blockDim.x + threadIdx.x;
    if (idx >= Bb * Ss * Hh * 32) return;
    const int j = idx & 31;
    const int h = (idx >> 5) & (Hh - 1);
    const int s = (idx >> 9) & (Ss - 1);
    const int b = idx >> 20;
    const float c = g_cos[s * 32 + j];
    const float sn = g_sin[s * 32 + j];
    const size_t base = ((size_t)(b * Ss + s)) * QKVD + h * HDIM + j;
    float q1 = g_qkv[base], q2 = g_qkv[base + 32];
    g_qkv[base]      = q1 * c - q2 * sn;
    g_qkv[base + 32] = q2 * c + q1 * sn;
    float k1 = g_qkv[base + Dd], k2 = g_qkv[base + Dd + 32];
    g_qkv[base + Dd]      = k1 * c - k2 * sn;
    g_qkv[base + Dd + 32] = k2 * c + k1 * sn;
}

// ---------------------------------------------------------------------------
// SGEMM: C[M,N] = A[M,K] * W[N,K]^T + bias[N]
// 128x128x8 tiles, 256 threads, 8x8 register micro-tile
// Requires M%128==0, N%128==0, K%8==0
// ---------------------------------------------------------------------------
__global__ void __launch_bounds__(256)
sgemm_tn_bias(const float* __restrict__ A, const float* __restrict__ W,
              const float* __restrict__ bias, float* __restrict__ C,
              int M, int N, int K) {
    __shared__ float As[8][128];
    __shared__ float Bs[8][128];
    const int bm = blockIdx.y * 128;
    const int bn = blockIdx.x * 128;
    const int tid = threadIdx.x;
    const int tx = tid & 15;
    const int ty = tid >> 4;
    float acc[8][8];
    #pragma unroll
    for (int i = 0; i < 8; i++)
        #pragma unroll
        for (int j = 0; j < 8; j++) acc[i][j] = 0.f;

    const int lr = tid >> 1;          // 0..127 tile row
    const int lc = (tid & 1) * 4;     // 0 or 4 within k-slab

    for (int k0 = 0; k0 < K; k0 += 8) {
        float4 av = *(const float4*)(A + (size_t)(bm + lr) * K + k0 + lc);
        float4 wv = *(const float4*)(W + (size_t)(bn + lr) * K + k0 + lc);
        As[lc + 0][lr] = av.x; As[lc + 1][lr] = av.y;
        As[lc + 2][lr] = av.z; As[lc + 3][lr] = av.w;
        Bs[lc + 0][lr] = wv.x; Bs[lc + 1][lr] = wv.y;
        Bs[lc + 2][lr] = wv.z; Bs[lc + 3][lr] = wv.w;
        __syncthreads();
        #pragma unroll
        for (int k = 0; k < 8; k++) {
            float4 a0 = *(const float4*)&As[k][ty * 8];
            float4 a1 = *(const float4*)&As[k][ty * 8 + 4];
            float4 b0 = *(const float4*)&Bs[k][tx * 8];
            float4 b1 = *(const float4*)&Bs[k][tx * 8 + 4];
            float a[8] = {a0.x, a0.y, a0.z, a0.w, a1.x, a1.y, a1.z, a1.w};
            float b[8] = {b0.x, b0.y, b0.z, b0.w, b1.x, b1.y, b1.z, b1.w};
            #pragma unroll
            for (int i = 0; i < 8; i++)
                #pragma unroll
                for (int j = 0; j < 8; j++)
                    acc[i][j] += a[i] * b[j];
        }
        __syncthreads();
    }
    #pragma unroll
    for (int i = 0; i < 8; i++) {
        float* cr = C + (size_t)(bm + ty * 8 + i) * N + bn + tx * 8;
        #pragma unroll
        for (int j = 0; j < 8; j++)
            cr[j] = acc[i][j] + bias[bn + tx * 8 + j];
    }
}

// ---------------------------------------------------------------------------
// Flash attention (causal). One thread owns one query row.
// Grid: (S/128, B*H). Block: 128 threads. BN = 32 keys per tile.
// q/k/v packed in g_qkv rows: [q(1024) | k(1024) | v(1024)], head h at h*64.
// Output to g_y laid out [b, s, h, hd] == [4096, 1024].
// ---------------------------------------------------------------------------
#define ATT_BM 128
#define ATT_BN 32

__global__ void __launch_bounds__(128)
flash_attn_kernel() {
    const int qblk = blockIdx.x;       // 0..15
    const int bh   = blockIdx.y;       // 0..31
    const int b = bh >> 4, h = bh & 15;
    const int tid = threadIdx.x;
    const int qi = qblk * ATT_BM + tid;   // global query position

    __shared__ float4 Ks[ATT_BN][16];
    __shared__ float4 Vs[ATT_BN][16];

    const float* qptr = g_qkv + ((size_t)(b * Ss) + qi) * QKVD + h * HDIM;
    float4 q[16];
    #pragma unroll
    for (int j = 0; j < 16; j++) q[j] = ((const float4*)qptr)[j];

    float4 o[16];
    #pragma unroll
    for (int j = 0; j < 16; j++) o[j] = make_float4(0.f, 0.f, 0.f, 0.f);
    float mrow = -INFINITY, lrow = 0.f;
    const float scale = 0.125f;   // 1/sqrt(64)

    const int ntiles = qblk * 4 + 4;
    const int ldr = tid >> 2;            // 0..31
    const int ldc = (tid & 3) * 4;       // float4 col index 0,4,8,12

    for (int kt = 0; kt < ntiles; kt++) {
        const float* kbase = g_qkv + ((size_t)(b * Ss) + kt * ATT_BN + ldr) * QKVD + Dd + h * HDIM;
        const float* vbase = kbase + Dd;
        #pragma unroll
        for (int u = 0; u < 4; u++) {
            Ks[ldr][ldc + u] = ((const float4*)kbase)[ldc + u];
            Vs[ldr][ldc + u] = ((const float4*)vbase)[ldc + u];
        }
        __syncthreads();

        float sc[ATT_BN];
        #pragma unroll 4
        for (int n = 0; n < ATT_BN; n++) {
            float d = 0.f;
            #pragma unroll
            for (int j = 0; j < 16; j++) {
                float4 kv = Ks[n][j];
                d += q[j].x * kv.x + q[j].y * kv.y + q[j].z * kv.z + q[j].w * kv.w;
            }
            sc[n] = d * scale;
        }
        if (kt >= qblk * 4) {
            const int kb0 = kt * ATT_BN;
            #pragma unroll
            for (int n = 0; n < ATT_BN; n++)
                if (kb0 + n > qi) sc[n] = -INFINITY;
        }
        float mnew = mrow;
        #pragma unroll
        for (int n = 0; n < ATT_BN; n++) mnew = fmaxf(mnew, sc[n]);
        const float corr = __expf(mrow - mnew);
        lrow *= corr;
        #pragma unroll
        for (int j = 0; j < 16; j++) {
            o[j].x *= corr; o[j].y *= corr; o[j].z *= corr; o[j].w *= corr;
        }
        #pragma unroll
        for (int n = 0; n < ATT_BN; n++) {
            sc[n] = __expf(sc[n] - mnew);   // reuse sc[] as p[]
            lrow += sc[n];
        }
        #pragma unroll 4
        for (int n = 0; n < ATT_BN; n++) {
            const float pn = sc[n];
            #pragma unroll
            for (int j = 0; j < 16; j++) {
                float4 vv = Vs[n][j];
                o[j].x += pn * vv.x; o[j].y += pn * vv.y;
                o[j].z += pn * vv.z; o[j].w += pn * vv.w;
            }
        }
        mrow = mnew;
        __syncthreads();
    }

    const float invl = 1.f / lrow;
    float4* yout = (float4*)(g_y + ((size_t)(b * Ss) + qi) * Dd + h * HDIM);
    #pragma unroll
    for (int j = 0; j < 16; j++)
        yout[j] = make_float4(o[j].x * invl, o[j].y * invl, o[j].z * invl, o[j].w * invl);
}

// ---------------------------------------------------------------------------
// Launch
// ---------------------------------------------------------------------------
extern "C" void kernel_launch(void* const* d_in, const int* in_sizes, int n_in,
                              void* d_out, int out_size) {
    const float* x      = (const float*)d_in[0];
    const float* norm_w = (const float*)d_in[1];
    const float* qkv_w  = (const float*)d_in[2];
    const float* qkv_b  = (const float*)d_in[3];
    const float* proj_w = (const float*)d_in[4];
    const float* proj_b = (const float*)d_in[5];
    float* out = (float*)d_out;

    float *p_xn, *p_qkv, *p_y;
    cudaGetSymbolAddress((void**)&p_xn, g_xn);
    cudaGetSymbolAddress((void**)&p_qkv, g_qkv);
    cudaGetSymbolAddress((void**)&p_y, g_y);

    // 1) RMSNorm
    rmsnorm_kernel<<<Mrows, 256>>>(x, norm_w);

    // 2) RoPE table
    rope_table_kernel<<<Ss, 32>>>();

    // 3) QKV GEMM: [4096,3072] = xn[4096,1024] @ qkv_w[3072,1024]^T + b
    sgemm_tn_bias<<<dim3(QKVD / 128, Mrows / 128), 256>>>(
        p_xn, qkv_w, qkv_b, p_qkv, Mrows, QKVD, Dd);

    // 4) RoPE on q,k
    {
        const int total = Bb * Ss * Hh * 32;
        rope_kernel<<<(total + 255) / 256, 256>>>();
    }

    // 5) Flash attention
    flash_attn_kernel<<<dim3(Ss / ATT_BM, Bb * Hh), 128>>>();

    // 6) Output projection: out[4096,1024] = y @ proj_w[1024,1024]^T + b
    sgemm_tn_bias<<<dim3(Dd / 128, Mrows / 128), 256>>>(
        p_y, proj_w, proj_b, out, Mrows, Dd, Dd);

    (void)in_sizes; (void)n_in; (void)out_size;
}

// round 3
// speedup vs baseline: 1.4161x; 1.4161x over previous
#include <cuda_runtime.h>
#include <cuda_bf16.h>
#include <cstdint>
#include <math.h>

#define Bb 2
#define Ss 2048
#define Dd 1024
#define Hh 16
#define HDIM 64
#define Mrows (Bb*Ss)   // 4096
#define QKVD (3*Dd)     // 3072

// ---------------------------------------------------------------------------
// Scratch (static device arrays are permitted)
// ---------------------------------------------------------------------------
__device__ float g_xn[(size_t)Mrows * Dd];
__device__ float g_qkv[(size_t)Mrows * QKVD];
__device__ float g_y[(size_t)Mrows * Dd];
__device__ float g_cos[Ss * 32];
__device__ float g_sin[Ss * 32];
__device__ __nv_bfloat16 g_hA[(size_t)Mrows * Dd];
__device__ __nv_bfloat16 g_lA[(size_t)Mrows * Dd];
__device__ __nv_bfloat16 g_hW[(size_t)QKVD * Dd];
__device__ __nv_bfloat16 g_lW[(size_t)QKVD * Dd];

// ---------------------------------------------------------------------------
// Helpers
// ---------------------------------------------------------------------------
__device__ __forceinline__ uint32_t smem_to_u32(const void* p) {
    uint32_t a;
    asm("{ .reg .u64 t; cvta.to.shared.u64 t, %1; cvt.u32.u64 %0, t; }"
        : "=r"(a) : "l"(p));
    return a;
}
__device__ __forceinline__ void ldsm_x4(uint32_t addr, uint32_t& r0, uint32_t& r1,
                                        uint32_t& r2, uint32_t& r3) {
    asm volatile("ldmatrix.sync.aligned.m8n8.x4.shared.b16 {%0,%1,%2,%3}, [%4];"
                 : "=r"(r0), "=r"(r1), "=r"(r2), "=r"(r3) : "r"(addr));
}
__device__ __forceinline__ void mma16816(float* c, const uint32_t* a, const uint32_t* b) {
    asm volatile("mma.sync.aligned.m16n8k16.row.col.f32.bf16.bf16.f32 "
                 "{%0,%1,%2,%3}, {%4,%5,%6,%7}, {%8,%9}, {%0,%1,%2,%3};"
                 : "+f"(c[0]), "+f"(c[1]), "+f"(c[2]), "+f"(c[3])
                 : "r"(a[0]), "r"(a[1]), "r"(a[2]), "r"(a[3]), "r"(b[0]), "r"(b[1]));
}
#define CP_ASYNC16(sa, ga) \
    asm volatile("cp.async.cg.shared.global [%0], [%1], 16;" :: "r"(sa), "l"(ga))
#define CP_COMMIT() asm volatile("cp.async.commit_group;" ::: "memory")
#define CP_WAIT1()  asm volatile("cp.async.wait_group 1;" ::: "memory")

// ---------------------------------------------------------------------------
// RMSNorm
// ---------------------------------------------------------------------------
__global__ void rmsnorm_kernel(const float* __restrict__ x,
                               const float* __restrict__ w) {
    const int row = blockIdx.x;
    const float* xr = x + (size_t)row * Dd;
    float ss = 0.f;
    for (int i = threadIdx.x; i < Dd; i += blockDim.x) {
        float v = xr[i];
        ss += v * v;
    }
    __shared__ float red[32];
    #pragma unroll
    for (int o = 16; o > 0; o >>= 1) ss += __shfl_xor_sync(0xffffffffu, ss, o);
    const int wid = threadIdx.x >> 5, lid = threadIdx.x & 31;
    if (lid == 0) red[wid] = ss;
    __syncthreads();
    if (wid == 0) {
        ss = (lid < (int)(blockDim.x >> 5)) ? red[lid] : 0.f;
        #pragma unroll
        for (int o = 16; o > 0; o >>= 1) ss += __shfl_xor_sync(0xffffffffu, ss, o);
        if (lid == 0) red[0] = ss;
    }
    __syncthreads();
    const float inv = rsqrtf(red[0] * (1.0f / Dd) + 1e-6f);
    float* out = g_xn + (size_t)row * Dd;
    for (int i = threadIdx.x; i < Dd; i += blockDim.x)
        out[i] = xr[i] * inv * w[i];
}

// ---------------------------------------------------------------------------
// RoPE table + apply
// ---------------------------------------------------------------------------
__global__ void rope_table_kernel() {
    const int t = blockIdx.x;
    const int i = threadIdx.x;
    double inv = pow(10000.0, -((double)(2 * i)) / 64.0);
    double a = (double)t * inv;
    g_cos[t * 32 + i] = (float)cos(a);
    g_sin[t * 32 + i] = (float)sin(a);
}

__global__ void rope_kernel() {
    const int idx = blockIdx.x * blockDim.x + threadIdx.x;
    if (idx >= Bb * Ss * Hh * 32) return;
    const int j = idx & 31;
    const int h = (idx >> 5) & (Hh - 1);
    const int s = (idx >> 9) & (Ss - 1);
    const int b = idx >> 20;
    const float c = g_cos[s * 32 + j];
    const float sn = g_sin[s * 32 + j];
    const size_t base = ((size_t)(b * Ss + s)) * QKVD + h * HDIM + j;
    float q1 = g_qkv[base], q2 = g_qkv[base + 32];
    g_qkv[base]      = q1 * c - q2 * sn;
    g_qkv[base + 32] = q2 * c + q1 * sn;
    float k1 = g_qkv[base + Dd], k2 = g_qkv[base + Dd + 32];
    g_qkv[base + Dd]      = k1 * c - k2 * sn;
    g_qkv[base + Dd + 32] = k2 * c + k1 * sn;
}

// ---------------------------------------------------------------------------
// fp32 -> (hi,lo) bf16 split
// ---------------------------------------------------------------------------
__device__ __forceinline__ uint32_t pack_bf2(__nv_bfloat16 a, __nv_bfloat16 b) {
    return ((uint32_t)__bfloat16_as_ushort(b) << 16) | (uint32_t)__bfloat16_as_ushort(a);
}
__global__ void split_bf16_kernel(const float4* __restrict__ src,
                                  uint2* __restrict__ hi, uint2* __restrict__ lo, int n4) {
    int i = blockIdx.x * blockDim.x + threadIdx.x;
    if (i >= n4) return;
    float4 v = src[i];
    __nv_bfloat16 h0 = __float2bfloat16(v.x);
    __nv_bfloat16 h1 = __float2bfloat16(v.y);
    __nv_bfloat16 h2 = __float2bfloat16(v.z);
    __nv_bfloat16 h3 = __float2bfloat16(v.w);
    __nv_bfloat16 l0 = __float2bfloat16(v.x - __bfloat162float(h0));
    __nv_bfloat16 l1 = __float2bfloat16(v.y - __bfloat162float(h1));
    __nv_bfloat16 l2 = __float2bfloat16(v.z - __bfloat162float(h2));
    __nv_bfloat16 l3 = __float2bfloat16(v.w - __bfloat162float(h3));
    hi[i] = make_uint2(pack_bf2(h0, h1), pack_bf2(h2, h3));
    lo[i] = make_uint2(pack_bf2(l0, l1), pack_bf2(l2, l3));
}

// ---------------------------------------------------------------------------
// Split-precision GEMM via mma.sync bf16:
//   C[M,N] = A[M,K] * W[N,K]^T + bias, A,W given as (hi,lo) bf16.
//   CTA 128x128, 8 warps (warp tile 32x64), KC=32, 3-stage cp.async pipeline.
// ---------------------------------------------------------------------------
#define PADB  80                     // bytes per smem row (32 bf16 + 8 pad)
#define TILEB (128 * PADB)           // 10240
#define STAGEB (4 * TILEB)           // 40960: Ah, Al, Wh, Wl
#define NSTAGE 3
#define GSMEM (NSTAGE * STAGEB)      // 122880

__global__ void __launch_bounds__(256, 1)
gemm_bf16x3(const __nv_bfloat16* __restrict__ Ahi, const __nv_bfloat16* __restrict__ Alo,
            const __nv_bfloat16* __restrict__ Whi, const __nv_bfloat16* __restrict__ Wlo,
            const float* __restrict__ bias, float* __restrict__ C,
            int M, int N, int K) {
    extern __shared__ char smem[];
    const uint32_t sb = smem_to_u32(smem);
    const int tid = threadIdx.x, lane = tid & 31, w = tid >> 5;
    const int bm = blockIdx.y * 128, bn = blockIdx.x * 128;
    const int wm = (w >> 1) * 32, wn = (w & 1) * 64;

    const __nv_bfloat16* srcs[4] = {Ahi, Alo, Whi, Wlo};
    const int rb[4] = {bm, bm, bn, bn};

    auto load_stage = [&](int s, int k0) {
        const uint32_t st = sb + s * STAGEB;
        #pragma unroll
        for (int t = 0; t < 4; t++) {
            const __nv_bfloat16* src = srcs[t] + (size_t)rb[t] * K + k0;
            const uint32_t tb = st + t * TILEB;
            #pragma unroll
            for (int j = 0; j < 2; j++) {
                const int c = tid + j * 256;
                const int row = c >> 2, c16 = c & 3;
                const uint32_t sa = tb + row * PADB + c16 * 16;
                const __nv_bfloat16* ga = src + (size_t)row * K + c16 * 8;
                CP_ASYNC16(sa, ga);
            }
        }
    };

    float acc[2][8][4];
    #pragma unroll
    for (int mi = 0; mi < 2; mi++)
        #pragma unroll
        for (int nj = 0; nj < 8; nj++)
            #pragma unroll
            for (int r = 0; r < 4; r++) acc[mi][nj][r] = 0.f;

    load_stage(0, 0);  CP_COMMIT();
    load_stage(1, 32); CP_COMMIT();

    const int nch = K >> 5;
    const int sel = lane >> 3;
    const int asub = (sel & 1) * 8, ak8 = (sel >> 1) * 8;
    const int nsub = (sel >> 1) * 8, bk8 = (sel & 1) * 8;

    for (int cidx = 0; cidx < nch; cidx++) {
        CP_WAIT1();
        __syncthreads();
        if (cidx + 2 < nch) load_stage((cidx + 2) % NSTAGE, (cidx + 2) * 32);
        CP_COMMIT();

        const uint32_t st = sb + (cidx % NSTAGE) * STAGEB;
        #pragma unroll
        for (int kk = 0; kk < 2; kk++) {
            const int ko = kk * 16;
            uint32_t ah[2][4], al[2][4], bh[8][2], bl[8][2];
            #pragma unroll
            for (int mi = 0; mi < 2; mi++) {
                const uint32_t addr = st + (wm + mi * 16 + (lane & 7) + asub) * PADB
                                      + (ko + ak8) * 2;
                ldsm_x4(addr, ah[mi][0], ah[mi][1], ah[mi][2], ah[mi][3]);
                ldsm_x4(addr + TILEB, al[mi][0], al[mi][1], al[mi][2], al[mi][3]);
            }
            #pragma unroll
            for (int ni = 0; ni < 4; ni++) {
                const uint32_t addr = st + 2 * TILEB
                                      + (wn + ni * 16 + (lane & 7) + nsub) * PADB
                                      + (ko + bk8) * 2;
                uint32_t r0, r1, r2, r3;
                ldsm_x4(addr, r0, r1, r2, r3);
                bh[ni * 2][0] = r0; bh[ni * 2][1] = r1;
                bh[ni * 2 + 1][0] = r2; bh[ni * 2 + 1][1] = r3;
                ldsm_x4(addr + TILEB, r0, r1, r2, r3);
                bl[ni * 2][0] = r0; bl[ni * 2][1] = r1;
                bl[ni * 2 + 1][0] = r2; bl[ni * 2 + 1][1] = r3;
            }
            #pragma unroll
            for (int mi = 0; mi < 2; mi++)
                #pragma unroll
                for (int nj = 0; nj < 8; nj++) {
                    mma16816(acc[mi][nj], ah[mi], bh[nj]);
                    mma16816(acc[mi][nj], ah[mi], bl[nj]);
                    mma16816(acc[mi][nj], al[mi], bh[nj]);
                }
        }
    }

    // epilogue
    #pragma unroll
    for (int mi = 0; mi < 2; mi++) {
        const int row = bm + wm + mi * 16 + (lane >> 2);
        #pragma unroll
        for (int nj = 0; nj < 8; nj++) {
            const int col = bn + wn + nj * 8 + (lane & 3) * 2;
            const float b0 = bias[col], b1 = bias[col + 1];
            float* c0 = C + (size_t)row * N + col;
            float* c1 = C + (size_t)(row + 8) * N + col;
            c0[0] = acc[mi][nj][0] + b0;
            c0[1] = acc[mi][nj][1] + b1;
            c1[0] = acc[mi][nj][2] + b0;
            c1[1] = acc[mi][nj][3] + b1;
        }
    }
}

// ---------------------------------------------------------------------------
// Flash attention (causal). One thread per query row. fp32.
// ---------------------------------------------------------------------------
#define ATT_BM 128
#define ATT_BN 32

__global__ void __launch_bounds__(128)
flash_attn_kernel() {
    const int qblk = blockIdx.x;
    const int bh   = blockIdx.y;
    const int b = bh >> 4, h = bh & 15;
    const int tid = threadIdx.x;
    const int qi = qblk * ATT_BM + tid;

    __shared__ float4 Ks[ATT_BN][16];
    __shared__ float4 Vs[ATT_BN][16];

    const float* qptr = g_qkv + ((size_t)(b * Ss) + qi) * QKVD + h * HDIM;
    float4 q[16];
    #pragma unroll
    for (int j = 0; j < 16; j++) q[j] = ((const float4*)qptr)[j];

    float4 o[16];
    #pragma unroll
    for (int j = 0; j < 16; j++) o[j] = make_float4(0.f, 0.f, 0.f, 0.f);
    float mrow = -INFINITY, lrow = 0.f;
    const float scale = 0.125f;

    const int ntiles = qblk * 4 + 4;
    const int ldr = tid >> 2;
    const int ldc = (tid & 3) * 4;

    for (int kt = 0; kt < ntiles; kt++) {
        const float* kbase = g_qkv + ((size_t)(b * Ss) + kt * ATT_BN + ldr) * QKVD + Dd + h * HDIM;
        const float* vbase = kbase + Dd;
        #pragma unroll
        for (int u = 0; u < 4; u++) {
            Ks[ldr][ldc + u] = ((const float4*)kbase)[ldc + u];
            Vs[ldr][ldc + u] = ((const float4*)vbase)[ldc + u];
        }
        __syncthreads();

        float sc[ATT_BN];
        #pragma unroll 4
        for (int n = 0; n < ATT_BN; n++) {
            float d = 0.f;
            #pragma unroll
            for (int j = 0; j < 16; j++) {
                float4 kv = Ks[n][j];
                d += q[j].x * kv.x + q[j].y * kv.y + q[j].z * kv.z + q[j].w * kv.w;
            }
            sc[n] = d * scale;
        }
        if (kt >= qblk * 4) {
            const int kb0 = kt * ATT_BN;
            #pragma unroll
            for (int n = 0; n < ATT_BN; n++)
                if (kb0 + n > qi) sc[n] = -INFINITY;
        }
        float mnew = mrow;
        #pragma unroll
        for (int n = 0; n < ATT_BN; n++) mnew = fmaxf(mnew, sc[n]);
        const float corr = __expf(mrow - mnew);
        lrow *= corr;
        #pragma unroll
        for (int j = 0; j < 16; j++) {
            o[j].x *= corr; o[j].y *= corr; o[j].z *= corr; o[j].w *= corr;
        }
        #pragma unroll
        for (int n = 0; n < ATT_BN; n++) {
            sc[n] = __expf(sc[n] - mnew);
            lrow += sc[n];
        }
        #pragma unroll 4
        for (int n = 0; n < ATT_BN; n++) {
            const float pn = sc[n];
            #pragma unroll
            for (int j = 0; j < 16; j++) {
                float4 vv = Vs[n][j];
                o[j].x += pn * vv.x; o[j].y += pn * vv.y;
                o[j].z += pn * vv.z; o[j].w += pn * vv.w;
            }
        }
        mrow = mnew;
        __syncthreads();
    }

    const float invl = 1.f / lrow;
    float4* yout = (float4*)(g_y + ((size_t)(b * Ss) + qi) * Dd + h * HDIM);
    #pragma unroll
    for (int j = 0; j < 16; j++)
        yout[j] = make_float4(o[j].x * invl, o[j].y * invl, o[j].z * invl, o[j].w * invl);
}

// ---------------------------------------------------------------------------
// Launch
// ---------------------------------------------------------------------------
extern "C" void kernel_launch(void* const* d_in, const int* in_sizes, int n_in,
                              void* d_out, int out_size) {
    const float* x      = (const float*)d_in[0];
    const float* norm_w = (const float*)d_in[1];
    const float* qkv_w  = (const float*)d_in[2];
    const float* qkv_b  = (const float*)d_in[3];
    const float* proj_w = (const float*)d_in[4];
    const float* proj_b = (const float*)d_in[5];
    float* out = (float*)d_out;

    float *p_xn, *p_qkv, *p_y;
    __nv_bfloat16 *p_hA, *p_lA, *p_hW, *p_lW;
    cudaGetSymbolAddress((void**)&p_xn, g_xn);
    cudaGetSymbolAddress((void**)&p_qkv, g_qkv);
    cudaGetSymbolAddress((void**)&p_y, g_y);
    cudaGetSymbolAddress((void**)&p_hA, g_hA);
    cudaGetSymbolAddress((void**)&p_lA, g_lA);
    cudaGetSymbolAddress((void**)&p_hW, g_hW);
    cudaGetSymbolAddress((void**)&p_lW, g_lW);

    cudaFuncSetAttribute(gemm_bf16x3, cudaFuncAttributeMaxDynamicSharedMemorySize, GSMEM);

    // 1) RMSNorm
    rmsnorm_kernel<<<Mrows, 256>>>(x, norm_w);
    // 2) RoPE table
    rope_table_kernel<<<Ss, 32>>>();
    // 3) split xn and qkv_w
    split_bf16_kernel<<<(Mrows * Dd / 4 + 255) / 256, 256>>>(
        (const float4*)p_xn, (uint2*)p_hA, (uint2*)p_lA, Mrows * Dd / 4);
    split_bf16_kernel<<<(QKVD * Dd / 4 + 255) / 256, 256>>>(
        (const float4*)qkv_w, (uint2*)p_hW, (uint2*)p_lW, QKVD * Dd / 4);
    // 4) QKV GEMM
    gemm_bf16x3<<<dim3(QKVD / 128, Mrows / 128), 256, GSMEM>>>(
        p_hA, p_lA, p_hW, p_lW, qkv_b, p_qkv, Mrows, QKVD, Dd);
    // 5) RoPE
    {
        const int total = Bb * Ss * Hh * 32;
        rope_kernel<<<(total + 255) / 256, 256>>>();
    }
    // 6) Flash attention
    flash_attn_kernel<<<dim3(Ss / ATT_BM, Bb * Hh), 128>>>();
    // 7) split y and proj_w
    split_bf16_kernel<<<(Mrows * Dd / 4 + 255) / 256, 256>>>(
        (const float4*)p_y, (uint2*)p_hA, (uint2*)p_lA, Mrows * Dd / 4);
    split_bf16_kernel<<<(Dd * Dd / 4 + 255) / 256, 256>>>(
        (const float4*)proj_w, (uint2*)p_hW, (uint2*)p_lW, Dd * Dd / 4);
    // 8) Output projection
    gemm_bf16x3<<<dim3(Dd / 128, Mrows / 128), 256, GSMEM>>>(
        p_hA, p_lA, p_hW, p_lW, proj_b, out, Mrows, Dd, Dd);

    (void)in_sizes; (void)n_in; (void)out_size;
}

// round 4
// speedup vs baseline: 1.4460x; 1.0211x over previous
#include <cuda_runtime.h>
#include <cuda_bf16.h>
#include <cstdint>
#include <math.h>

#define Bb 2
#define Ss 2048
#define Dd 1024
#define Hh 16
#define HDIM 64
#define Mrows (Bb*Ss)   // 4096
#define QKVD (3*Dd)     // 3072

// ---------------------------------------------------------------------------
// Scratch (static device arrays are permitted)
// ---------------------------------------------------------------------------
__device__ float g_xn[(size_t)Mrows * Dd];
__device__ float g_qkv[(size_t)Mrows * QKVD];
__device__ float g_y[(size_t)Mrows * Dd];
__device__ float g_cos[Ss * 32];
__device__ float g_sin[Ss * 32];
__device__ __nv_bfloat16 g_hA[(size_t)Mrows * Dd];
__device__ __nv_bfloat16 g_lA[(size_t)Mrows * Dd];
__device__ __nv_bfloat16 g_hW[(size_t)QKVD * Dd];
__device__ __nv_bfloat16 g_lW[(size_t)QKVD * Dd];

// ---------------------------------------------------------------------------
// Helpers
// ---------------------------------------------------------------------------
__device__ __forceinline__ uint32_t smem_to_u32(const void* p) {
    uint32_t a;
    asm("{ .reg .u64 t; cvta.to.shared.u64 t, %1; cvt.u32.u64 %0, t; }"
        : "=r"(a) : "l"(p));
    return a;
}
__device__ __forceinline__ void ldsm_x4(uint32_t addr, uint32_t& r0, uint32_t& r1,
                                        uint32_t& r2, uint32_t& r3) {
    asm volatile("ldmatrix.sync.aligned.m8n8.x4.shared.b16 {%0,%1,%2,%3}, [%4];"
                 : "=r"(r0), "=r"(r1), "=r"(r2), "=r"(r3) : "r"(addr));
}
__device__ __forceinline__ void mma16816(float* c, const uint32_t* a, const uint32_t* b) {
    asm volatile("mma.sync.aligned.m16n8k16.row.col.f32.bf16.bf16.f32 "
                 "{%0,%1,%2,%3}, {%4,%5,%6,%7}, {%8,%9}, {%0,%1,%2,%3};"
                 : "+f"(c[0]), "+f"(c[1]), "+f"(c[2]), "+f"(c[3])
                 : "r"(a[0]), "r"(a[1]), "r"(a[2]), "r"(a[3]), "r"(b[0]), "r"(b[1]));
}
#define CP_ASYNC16(sa, ga) \
    asm volatile("cp.async.cg.shared.global [%0], [%1], 16;" :: "r"(sa), "l"(ga))
#define CP_COMMIT() asm volatile("cp.async.commit_group;" ::: "memory")
#define CP_WAIT1()  asm volatile("cp.async.wait_group 1;" ::: "memory")

// ---------------------------------------------------------------------------
// RMSNorm
// ---------------------------------------------------------------------------
__global__ void rmsnorm_kernel(const float* __restrict__ x,
                               const float* __restrict__ w) {
    const int row = blockIdx.x;
    const float* xr = x + (size_t)row * Dd;
    float ss = 0.f;
    for (int i = threadIdx.x; i < Dd; i += blockDim.x) {
        float v = xr[i];
        ss += v * v;
    }
    __shared__ float red[32];
    #pragma unroll
    for (int o = 16; o > 0; o >>= 1) ss += __shfl_xor_sync(0xffffffffu, ss, o);
    const int wid = threadIdx.x >> 5, lid = threadIdx.x & 31;
    if (lid == 0) red[wid] = ss;
    __syncthreads();
    if (wid == 0) {
        ss = (lid < (int)(blockDim.x >> 5)) ? red[lid] : 0.f;
        #pragma unroll
        for (int o = 16; o > 0; o >>= 1) ss += __shfl_xor_sync(0xffffffffu, ss, o);
        if (lid == 0) red[0] = ss;
    }
    __syncthreads();
    const float inv = rsqrtf(red[0] * (1.0f / Dd) + 1e-6f);
    float* out = g_xn + (size_t)row * Dd;
    for (int i = threadIdx.x; i < Dd; i += blockDim.x)
        out[i] = xr[i] * inv * w[i];
}

// ---------------------------------------------------------------------------
// RoPE table + apply
// ---------------------------------------------------------------------------
__global__ void rope_table_kernel() {
    const int t = blockIdx.x;
    const int i = threadIdx.x;
    double inv = pow(10000.0, -((double)(2 * i)) / 64.0);
    double a = (double)t * inv;
    g_cos[t * 32 + i] = (float)cos(a);
    g_sin[t * 32 + i] = (float)sin(a);
}

__global__ void rope_kernel() {
    const int idx = blockIdx.x * blockDim.x + threadIdx.x;
    if (idx >= Bb * Ss * Hh * 32) return;
    const int j = idx & 31;
    const int h = (idx >> 5) & (Hh - 1);
    const int s = (idx >> 9) & (Ss - 1);
    const int b = idx >> 20;
    const float c = g_cos[s * 32 + j];
    const float sn = g_sin[s * 32 + j];
    const size_t base = ((size_t)(b * Ss + s)) * QKVD + h * HDIM + j;
    float q1 = g_qkv[base], q2 = g_qkv[base + 32];
    g_qkv[base]      = q1 * c - q2 * sn;
    g_qkv[base + 32] = q2 * c + q1 * sn;
    float k1 = g_qkv[base + Dd], k2 = g_qkv[base + Dd + 32];
    g_qkv[base + Dd]      = k1 * c - k2 * sn;
    g_qkv[base + Dd + 32] = k2 * c + k1 * sn;
}

// ---------------------------------------------------------------------------
// fp32 -> (hi,lo) bf16 split
// ---------------------------------------------------------------------------
__device__ __forceinline__ uint32_t pack_bf2(__nv_bfloat16 a, __nv_bfloat16 b) {
    return ((uint32_t)__bfloat16_as_ushort(b) << 16) | (uint32_t)__bfloat16_as_ushort(a);
}
__global__ void split_bf16_kernel(const float4* __restrict__ src,
                                  uint2* __restrict__ hi, uint2* __restrict__ lo, int n4) {
    int i = blockIdx.x * blockDim.x + threadIdx.x;
    if (i >= n4) return;
    float4 v = src[i];
    __nv_bfloat16 h0 = __float2bfloat16(v.x);
    __nv_bfloat16 h1 = __float2bfloat16(v.y);
    __nv_bfloat16 h2 = __float2bfloat16(v.z);
    __nv_bfloat16 h3 = __float2bfloat16(v.w);
    __nv_bfloat16 l0 = __float2bfloat16(v.x - __bfloat162float(h0));
    __nv_bfloat16 l1 = __float2bfloat16(v.y - __bfloat162float(h1));
    __nv_bfloat16 l2 = __float2bfloat16(v.z - __bfloat162float(h2));
    __nv_bfloat16 l3 = __float2bfloat16(v.w - __bfloat162float(h3));
    hi[i] = make_uint2(pack_bf2(h0, h1), pack_bf2(h2, h3));
    lo[i] = make_uint2(pack_bf2(l0, l1), pack_bf2(l2, l3));
}

// ---------------------------------------------------------------------------
// Split-precision GEMM via mma.sync bf16:
//   C[M,N] = A[M,K] * W[N,K]^T + bias, A,W given as (hi,lo) bf16.
//   CTA 128x128, 8 warps (warp tile 32x64), KC=32, 3-stage cp.async pipeline.
//   Inner MMAs ordered pass-outermost: 16 independent accumulators between
//   reuses -> HMMA latency fully hidden.
// ---------------------------------------------------------------------------
#define PADB  80                     // bytes per smem row (32 bf16 + 8 pad)
#define TILEB (128 * PADB)           // 10240
#define STAGEB (4 * TILEB)           // 40960: Ah, Al, Wh, Wl
#define NSTAGE 3
#define GSMEM (NSTAGE * STAGEB)      // 122880

__global__ void __launch_bounds__(256, 1)
gemm_bf16x3(const __nv_bfloat16* __restrict__ Ahi, const __nv_bfloat16* __restrict__ Alo,
            const __nv_bfloat16* __restrict__ Whi, const __nv_bfloat16* __restrict__ Wlo,
            const float* __restrict__ bias, float* __restrict__ C,
            int M, int N, int K) {
    extern __shared__ char smem[];
    const uint32_t sb = smem_to_u32(smem);
    const int tid = threadIdx.x, lane = tid & 31, w = tid >> 5;
    const int bm = blockIdx.y * 128, bn = blockIdx.x * 128;
    const int wm = (w >> 1) * 32, wn = (w & 1) * 64;

    const __nv_bfloat16* srcs[4] = {Ahi, Alo, Whi, Wlo};
    const int rb[4] = {bm, bm, bn, bn};

    auto load_stage = [&](int s, int k0) {
        const uint32_t st = sb + s * STAGEB;
        #pragma unroll
        for (int t = 0; t < 4; t++) {
            const __nv_bfloat16* src = srcs[t] + (size_t)rb[t] * K + k0;
            const uint32_t tb = st + t * TILEB;
            #pragma unroll
            for (int j = 0; j < 2; j++) {
                const int c = tid + j * 256;
                const int row = c >> 2, c16 = c & 3;
                const uint32_t sa = tb + row * PADB + c16 * 16;
                const __nv_bfloat16* ga = src + (size_t)row * K + c16 * 8;
                CP_ASYNC16(sa, ga);
            }
        }
    };

    float acc[2][8][4];
    #pragma unroll
    for (int mi = 0; mi < 2; mi++)
        #pragma unroll
        for (int nj = 0; nj < 8; nj++)
            #pragma unroll
            for (int r = 0; r < 4; r++) acc[mi][nj][r] = 0.f;

    load_stage(0, 0);  CP_COMMIT();
    load_stage(1, 32); CP_COMMIT();

    const int nch = K >> 5;
    const int sel = lane >> 3;
    const int asub = (sel & 1) * 8, ak8 = (sel >> 1) * 8;
    const int nsub = (sel >> 1) * 8, bk8 = (sel & 1) * 8;

    for (int cidx = 0; cidx < nch; cidx++) {
        CP_WAIT1();
        __syncthreads();
        if (cidx + 2 < nch) load_stage((cidx + 2) % NSTAGE, (cidx + 2) * 32);
        CP_COMMIT();

        const uint32_t st = sb + (cidx % NSTAGE) * STAGEB;
        #pragma unroll
        for (int kk = 0; kk < 2; kk++) {
            const int ko = kk * 16;
            uint32_t ah[2][4], al[2][4], bh[8][2], bl[8][2];
            #pragma unroll
            for (int mi = 0; mi < 2; mi++) {
                const uint32_t addr = st + (wm + mi * 16 + (lane & 7) + asub) * PADB
                                      + (ko + ak8) * 2;
                ldsm_x4(addr, ah[mi][0], ah[mi][1], ah[mi][2], ah[mi][3]);
                ldsm_x4(addr + TILEB, al[mi][0], al[mi][1], al[mi][2], al[mi][3]);
            }
            #pragma unroll
            for (int ni = 0; ni < 4; ni++) {
                const uint32_t addr = st + 2 * TILEB
                                      + (wn + ni * 16 + (lane & 7) + nsub) * PADB
                                      + (ko + bk8) * 2;
                uint32_t r0, r1, r2, r3;
                ldsm_x4(addr, r0, r1, r2, r3);
                bh[ni * 2][0] = r0; bh[ni * 2][1] = r1;
                bh[ni * 2 + 1][0] = r2; bh[ni * 2 + 1][1] = r3;
                ldsm_x4(addr + TILEB, r0, r1, r2, r3);
                bl[ni * 2][0] = r0; bl[ni * 2][1] = r1;
                bl[ni * 2 + 1][0] = r2; bl[ni * 2 + 1][1] = r3;
            }
            // Pass-outermost ordering: 16 independent accumulators between
            // consecutive writes to the same acc -> no RAW stall chains.
            #pragma unroll
            for (int mi = 0; mi < 2; mi++)
                #pragma unroll
                for (int nj = 0; nj < 8; nj++)
                    mma16816(acc[mi][nj], ah[mi], bh[nj]);
            #pragma unroll
            for (int mi = 0; mi < 2; mi++)
                #pragma unroll
                for (int nj = 0; nj < 8; nj++)
                    mma16816(acc[mi][nj], ah[mi], bl[nj]);
            #pragma unroll
            for (int mi = 0; mi < 2; mi++)
                #pragma unroll
                for (int nj = 0; nj < 8; nj++)
                    mma16816(acc[mi][nj], al[mi], bh[nj]);
        }
    }

    // epilogue (vectorized float2 stores)
    #pragma unroll
    for (int mi = 0; mi < 2; mi++) {
        const int row = bm + wm + mi * 16 + (lane >> 2);
        #pragma unroll
        for (int nj = 0; nj < 8; nj++) {
            const int col = bn + wn + nj * 8 + (lane & 3) * 2;
            const float b0 = bias[col], b1 = bias[col + 1];
            float2* c0 = (float2*)(C + (size_t)row * N + col);
            float2* c1 = (float2*)(C + (size_t)(row + 8) * N + col);
            *c0 = make_float2(acc[mi][nj][0] + b0, acc[mi][nj][1] + b1);
            *c1 = make_float2(acc[mi][nj][2] + b0, acc[mi][nj][3] + b1);
        }
    }
}

// ---------------------------------------------------------------------------
// Flash attention (causal). One thread per query row. fp32.
// ---------------------------------------------------------------------------
#define ATT_BM 128
#define ATT_BN 32

__global__ void __launch_bounds__(128)
flash_attn_kernel() {
    const int qblk = blockIdx.x;
    const int bh   = blockIdx.y;
    const int b = bh >> 4, h = bh & 15;
    const int tid = threadIdx.x;
    const int qi = qblk * ATT_BM + tid;

    __shared__ float4 Ks[ATT_BN][16];
    __shared__ float4 Vs[ATT_BN][16];

    const float* qptr = g_qkv + ((size_t)(b * Ss) + qi) * QKVD + h * HDIM;
    float4 q[16];
    #pragma unroll
    for (int j = 0; j < 16; j++) q[j] = ((const float4*)qptr)[j];

    float4 o[16];
    #pragma unroll
    for (int j = 0; j < 16; j++) o[j] = make_float4(0.f, 0.f, 0.f, 0.f);
    float mrow = -INFINITY, lrow = 0.f;
    const float scale = 0.125f;

    const int ntiles = qblk * 4 + 4;
    const int ldr = tid >> 2;
    const int ldc = (tid & 3) * 4;

    for (int kt = 0; kt < ntiles; kt++) {
        const float* kbase = g_qkv + ((size_t)(b * Ss) + kt * ATT_BN + ldr) * QKVD + Dd + h * HDIM;
        const float* vbase = kbase + Dd;
        #pragma unroll
        for (int u = 0; u < 4; u++) {
            Ks[ldr][ldc + u] = ((const float4*)kbase)[ldc + u];
            Vs[ldr][ldc + u] = ((const float4*)vbase)[ldc + u];
        }
        __syncthreads();

        float sc[ATT_BN];
        #pragma unroll 4
        for (int n = 0; n < ATT_BN; n++) {
            float d = 0.f;
            #pragma unroll
            for (int j = 0; j < 16; j++) {
                float4 kv = Ks[n][j];
                d += q[j].x * kv.x + q[j].y * kv.y + q[j].z * kv.z + q[j].w * kv.w;
            }
            sc[n] = d * scale;
        }
        if (kt >= qblk * 4) {
            const int kb0 = kt * ATT_BN;
            #pragma unroll
            for (int n = 0; n < ATT_BN; n++)
                if (kb0 + n > qi) sc[n] = -INFINITY;
        }
        float mnew = mrow;
        #pragma unroll
        for (int n = 0; n < ATT_BN; n++) mnew = fmaxf(mnew, sc[n]);
        const float corr = __expf(mrow - mnew);
        lrow *= corr;
        #pragma unroll
        for (int j = 0; j < 16; j++) {
            o[j].x *= corr; o[j].y *= corr; o[j].z *= corr; o[j].w *= corr;
        }
        #pragma unroll
        for (int n = 0; n < ATT_BN; n++) {
            sc[n] = __expf(sc[n] - mnew);
            lrow += sc[n];
        }
        #pragma unroll 4
        for (int n = 0; n < ATT_BN; n++) {
            const float pn = sc[n];
            #pragma unroll
            for (int j = 0; j < 16; j++) {
                float4 vv = Vs[n][j];
                o[j].x += pn * vv.x; o[j].y += pn * vv.y;
                o[j].z += pn * vv.z; o[j].w += pn * vv.w;
            }
        }
        mrow = mnew;
        __syncthreads();
    }

    const float invl = 1.f / lrow;
    float4* yout = (float4*)(g_y + ((size_t)(b * Ss) + qi) * Dd + h * HDIM);
    #pragma unroll
    for (int j = 0; j < 16; j++)
        yout[j] = make_float4(o[j].x * invl, o[j].y * invl, o[j].z * invl, o[j].w * invl);
}

// ---------------------------------------------------------------------------
// Launch
// ---------------------------------------------------------------------------
extern "C" void kernel_launch(void* const* d_in, const int* in_sizes, int n_in,
                              void* d_out, int out_size) {
    const float* x      = (const float*)d_in[0];
    const float* norm_w = (const float*)d_in[1];
    const float* qkv_w  = (const float*)d_in[2];
    const float* qkv_b  = (const float*)d_in[3];
    const float* proj_w = (const float*)d_in[4];
    const float* proj_b = (const float*)d_in[5];
    float* out = (float*)d_out;

    float *p_xn, *p_qkv, *p_y;
    __nv_bfloat16 *p_hA, *p_lA, *p_hW, *p_lW;
    cudaGetSymbolAddress((void**)&p_xn, g_xn);
    cudaGetSymbolAddress((void**)&p_qkv, g_qkv);
    cudaGetSymbolAddress((void**)&p_y, g_y);
    cudaGetSymbolAddress((void**)&p_hA, g_hA);
    cudaGetSymbolAddress((void**)&p_lA, g_lA);
    cudaGetSymbolAddress((void**)&p_hW, g_hW);
    cudaGetSymbolAddress((void**)&p_lW, g_lW);

    cudaFuncSetAttribute(gemm_bf16x3, cudaFuncAttributeMaxDynamicSharedMemorySize, GSMEM);

    // 1) RMSNorm
    rmsnorm_kernel<<<Mrows, 256>>>(x, norm_w);
    // 2) RoPE table
    rope_table_kernel<<<Ss, 32>>>();
    // 3) split xn and qkv_w
    split_bf16_kernel<<<(Mrows * Dd / 4 + 255) / 256, 256>>>(
        (const float4*)p_xn, (uint2*)p_hA, (uint2*)p_lA, Mrows * Dd / 4);
    split_bf16_kernel<<<(QKVD * Dd / 4 + 255) / 256, 256>>>(
        (const float4*)qkv_w, (uint2*)p_hW, (uint2*)p_lW, QKVD * Dd / 4);
    // 4) QKV GEMM
    gemm_bf16x3<<<dim3(QKVD / 128, Mrows / 128), 256, GSMEM>>>(
        p_hA, p_lA, p_hW, p_lW, qkv_b, p_qkv, Mrows, QKVD, Dd);
    // 5) RoPE
    {
        const int total = Bb * Ss * Hh * 32;
        rope_kernel<<<(total + 255) / 256, 256>>>();
    }
    // 6) Flash attention
    flash_attn_kernel<<<dim3(Ss / ATT_BM, Bb * Hh), 128>>>();
    // 7) split y and proj_w
    split_bf16_kernel<<<(Mrows * Dd / 4 + 255) / 256, 256>>>(
        (const float4*)p_y, (uint2*)p_hA, (uint2*)p_lA, Mrows * Dd / 4);
    split_bf16_kernel<<<(Dd * Dd / 4 + 255) / 256, 256>>>(
        (const float4*)proj_w, (uint2*)p_hW, (uint2*)p_lW, Dd * Dd / 4);
    // 8) Output projection
    gemm_bf16x3<<<dim3(Dd / 128, Mrows / 128), 256, GSMEM>>>(
        p_hA, p_lA, p_hW, p_lW, proj_b, out, Mrows, Dd, Dd);

    (void)in_sizes; (void)n_in; (void)out_size;
}

// round 5
// speedup vs baseline: 1.5328x; 1.0600x over previous
#include <cuda_runtime.h>
#include <cuda_bf16.h>
#include <cstdint>
#include <math.h>

#define Bb 2
#define Ss 2048
#define Dd 1024
#define Hh 16
#define HDIM 64
#define Mrows (Bb*Ss)   // 4096
#define QKVD (3*Dd)     // 3072

// ---------------------------------------------------------------------------
// Scratch (static device arrays are permitted)
// ---------------------------------------------------------------------------
__device__ float g_xn[(size_t)Mrows * Dd];
__device__ float g_qkv[(size_t)Mrows * QKVD];
__device__ float g_y[(size_t)Mrows * Dd];
__device__ float g_cos[Ss * 32];
__device__ float g_sin[Ss * 32];
__device__ __nv_bfloat16 g_hA[(size_t)Mrows * Dd];
__device__ __nv_bfloat16 g_lA[(size_t)Mrows * Dd];
__device__ __nv_bfloat16 g_hW[(size_t)QKVD * Dd];
__device__ __nv_bfloat16 g_lW[(size_t)QKVD * Dd];

// ---------------------------------------------------------------------------
// Helpers
// ---------------------------------------------------------------------------
typedef unsigned long long u64t;

__device__ __forceinline__ uint32_t smem_to_u32(const void* p) {
    uint32_t a;
    asm("{ .reg .u64 t; cvta.to.shared.u64 t, %1; cvt.u32.u64 %0, t; }"
        : "=r"(a) : "l"(p));
    return a;
}
__device__ __forceinline__ void ldsm_x4(uint32_t addr, uint32_t& r0, uint32_t& r1,
                                        uint32_t& r2, uint32_t& r3) {
    asm volatile("ldmatrix.sync.aligned.m8n8.x4.shared.b16 {%0,%1,%2,%3}, [%4];"
                 : "=r"(r0), "=r"(r1), "=r"(r2), "=r"(r3) : "r"(addr));
}
__device__ __forceinline__ void mma16816(float* c, const uint32_t* a, const uint32_t* b) {
    asm volatile("mma.sync.aligned.m16n8k16.row.col.f32.bf16.bf16.f32 "
                 "{%0,%1,%2,%3}, {%4,%5,%6,%7}, {%8,%9}, {%0,%1,%2,%3};"
                 : "+f"(c[0]), "+f"(c[1]), "+f"(c[2]), "+f"(c[3])
                 : "r"(a[0]), "r"(a[1]), "r"(a[2]), "r"(a[3]), "r"(b[0]), "r"(b[1]));
}
#define CP_ASYNC16(sa, ga) \
    asm volatile("cp.async.cg.shared.global [%0], [%1], 16;" :: "r"(sa), "l"(ga))
#define CP_COMMIT() asm volatile("cp.async.commit_group;" ::: "memory")
#define CP_WAIT1()  asm volatile("cp.async.wait_group 1;" ::: "memory")

// Packed f32x2 ops (Blackwell base ISA)
__device__ __forceinline__ u64t pack2(float x, float y) {
    u64t r;
    asm("mov.b64 %0, {%1,%2};" : "=l"(r) : "f"(x), "f"(y));
    return r;
}
__device__ __forceinline__ float2 unpack2(u64t v) {
    float2 r;
    asm("mov.b64 {%0,%1}, %2;" : "=f"(r.x), "=f"(r.y) : "l"(v));
    return r;
}
__device__ __forceinline__ void fma2(u64t& d, u64t a, u64t b) {
    asm("fma.rn.f32x2 %0, %1, %2, %0;" : "+l"(d) : "l"(a), "l"(b));
}
__device__ __forceinline__ void mul2(u64t& d, u64t a) {
    asm("mul.rn.f32x2 %0, %0, %1;" : "+l"(d) : "l"(a));
}
__device__ __forceinline__ void add2(u64t& d, u64t a) {
    asm("add.rn.f32x2 %0, %0, %1;" : "+l"(d) : "l"(a));
}

// ---------------------------------------------------------------------------
// RMSNorm
// ---------------------------------------------------------------------------
__global__ void rmsnorm_kernel(const float* __restrict__ x,
                               const float* __restrict__ w) {
    const int row = blockIdx.x;
    const float* xr = x + (size_t)row * Dd;
    float ss = 0.f;
    for (int i = threadIdx.x; i < Dd; i += blockDim.x) {
        float v = xr[i];
        ss += v * v;
    }
    __shared__ float red[32];
    #pragma unroll
    for (int o = 16; o > 0; o >>= 1) ss += __shfl_xor_sync(0xffffffffu, ss, o);
    const int wid = threadIdx.x >> 5, lid = threadIdx.x & 31;
    if (lid == 0) red[wid] = ss;
    __syncthreads();
    if (wid == 0) {
        ss = (lid < (int)(blockDim.x >> 5)) ? red[lid] : 0.f;
        #pragma unroll
        for (int o = 16; o > 0; o >>= 1) ss += __shfl_xor_sync(0xffffffffu, ss, o);
        if (lid == 0) red[0] = ss;
    }
    __syncthreads();
    const float inv = rsqrtf(red[0] * (1.0f / Dd) + 1e-6f);
    float* out = g_xn + (size_t)row * Dd;
    for (int i = threadIdx.x; i < Dd; i += blockDim.x)
        out[i] = xr[i] * inv * w[i];
}

// ---------------------------------------------------------------------------
// RoPE table + apply
// ---------------------------------------------------------------------------
__global__ void rope_table_kernel() {
    const int t = blockIdx.x;
    const int i = threadIdx.x;
    double inv = pow(10000.0, -((double)(2 * i)) / 64.0);
    double a = (double)t * inv;
    g_cos[t * 32 + i] = (float)cos(a);
    g_sin[t * 32 + i] = (float)sin(a);
}

__global__ void rope_kernel() {
    const int idx = blockIdx.x * blockDim.x + threadIdx.x;
    if (idx >= Bb * Ss * Hh * 32) return;
    const int j = idx & 31;
    const int h = (idx >> 5) & (Hh - 1);
    const int s = (idx >> 9) & (Ss - 1);
    const int b = idx >> 20;
    const float c = g_cos[s * 32 + j];
    const float sn = g_sin[s * 32 + j];
    const size_t base = ((size_t)(b * Ss + s)) * QKVD + h * HDIM + j;
    float q1 = g_qkv[base], q2 = g_qkv[base + 32];
    g_qkv[base]      = q1 * c - q2 * sn;
    g_qkv[base + 32] = q2 * c + q1 * sn;
    float k1 = g_qkv[base + Dd], k2 = g_qkv[base + Dd + 32];
    g_qkv[base + Dd]      = k1 * c - k2 * sn;
    g_qkv[base + Dd + 32] = k2 * c + k1 * sn;
}

// ---------------------------------------------------------------------------
// fp32 -> (hi,lo) bf16 split
// ---------------------------------------------------------------------------
__device__ __forceinline__ uint32_t pack_bf2(__nv_bfloat16 a, __nv_bfloat16 b) {
    return ((uint32_t)__bfloat16_as_ushort(b) << 16) | (uint32_t)__bfloat16_as_ushort(a);
}
__global__ void split_bf16_kernel(const float4* __restrict__ src,
                                  uint2* __restrict__ hi, uint2* __restrict__ lo, int n4) {
    int i = blockIdx.x * blockDim.x + threadIdx.x;
    if (i >= n4) return;
    float4 v = src[i];
    __nv_bfloat16 h0 = __float2bfloat16(v.x);
    __nv_bfloat16 h1 = __float2bfloat16(v.y);
    __nv_bfloat16 h2 = __float2bfloat16(v.z);
    __nv_bfloat16 h3 = __float2bfloat16(v.w);
    __nv_bfloat16 l0 = __float2bfloat16(v.x - __bfloat162float(h0));
    __nv_bfloat16 l1 = __float2bfloat16(v.y - __bfloat162float(h1));
    __nv_bfloat16 l2 = __float2bfloat16(v.z - __bfloat162float(h2));
    __nv_bfloat16 l3 = __float2bfloat16(v.w - __bfloat162float(h3));
    hi[i] = make_uint2(pack_bf2(h0, h1), pack_bf2(h2, h3));
    lo[i] = make_uint2(pack_bf2(l0, l1), pack_bf2(l2, l3));
}

// ---------------------------------------------------------------------------
// Split-precision GEMM via mma.sync bf16 (unchanged from R4)
// ---------------------------------------------------------------------------
#define PADB  80
#define TILEB (128 * PADB)
#define STAGEB (4 * TILEB)
#define NSTAGE 3
#define GSMEM (NSTAGE * STAGEB)

__global__ void __launch_bounds__(256, 1)
gemm_bf16x3(const __nv_bfloat16* __restrict__ Ahi, const __nv_bfloat16* __restrict__ Alo,
            const __nv_bfloat16* __restrict__ Whi, const __nv_bfloat16* __restrict__ Wlo,
            const float* __restrict__ bias, float* __restrict__ C,
            int M, int N, int K) {
    extern __shared__ char smem[];
    const uint32_t sb = smem_to_u32(smem);
    const int tid = threadIdx.x, lane = tid & 31, w = tid >> 5;
    const int bm = blockIdx.y * 128, bn = blockIdx.x * 128;
    const int wm = (w >> 1) * 32, wn = (w & 1) * 64;

    const __nv_bfloat16* srcs[4] = {Ahi, Alo, Whi, Wlo};
    const int rb[4] = {bm, bm, bn, bn};

    auto load_stage = [&](int s, int k0) {
        const uint32_t st = sb + s * STAGEB;
        #pragma unroll
        for (int t = 0; t < 4; t++) {
            const __nv_bfloat16* src = srcs[t] + (size_t)rb[t] * K + k0;
            const uint32_t tb = st + t * TILEB;
            #pragma unroll
            for (int j = 0; j < 2; j++) {
                const int c = tid + j * 256;
                const int row = c >> 2, c16 = c & 3;
                const uint32_t sa = tb + row * PADB + c16 * 16;
                const __nv_bfloat16* ga = src + (size_t)row * K + c16 * 8;
                CP_ASYNC16(sa, ga);
            }
        }
    };

    float acc[2][8][4];
    #pragma unroll
    for (int mi = 0; mi < 2; mi++)
        #pragma unroll
        for (int nj = 0; nj < 8; nj++)
            #pragma unroll
            for (int r = 0; r < 4; r++) acc[mi][nj][r] = 0.f;

    load_stage(0, 0);  CP_COMMIT();
    load_stage(1, 32); CP_COMMIT();

    const int nch = K >> 5;
    const int sel = lane >> 3;
    const int asub = (sel & 1) * 8, ak8 = (sel >> 1) * 8;
    const int nsub = (sel >> 1) * 8, bk8 = (sel & 1) * 8;

    for (int cidx = 0; cidx < nch; cidx++) {
        CP_WAIT1();
        __syncthreads();
        if (cidx + 2 < nch) load_stage((cidx + 2) % NSTAGE, (cidx + 2) * 32);
        CP_COMMIT();

        const uint32_t st = sb + (cidx % NSTAGE) * STAGEB;
        #pragma unroll
        for (int kk = 0; kk < 2; kk++) {
            const int ko = kk * 16;
            uint32_t ah[2][4], al[2][4], bh[8][2], bl[8][2];
            #pragma unroll
            for (int mi = 0; mi < 2; mi++) {
                const uint32_t addr = st + (wm + mi * 16 + (lane & 7) + asub) * PADB
                                      + (ko + ak8) * 2;
                ldsm_x4(addr, ah[mi][0], ah[mi][1], ah[mi][2], ah[mi][3]);
                ldsm_x4(addr + TILEB, al[mi][0], al[mi][1], al[mi][2], al[mi][3]);
            }
            #pragma unroll
            for (int ni = 0; ni < 4; ni++) {
                const uint32_t addr = st + 2 * TILEB
                                      + (wn + ni * 16 + (lane & 7) + nsub) * PADB
                                      + (ko + bk8) * 2;
                uint32_t r0, r1, r2, r3;
                ldsm_x4(addr, r0, r1, r2, r3);
                bh[ni * 2][0] = r0; bh[ni * 2][1] = r1;
                bh[ni * 2 + 1][0] = r2; bh[ni * 2 + 1][1] = r3;
                ldsm_x4(addr + TILEB, r0, r1, r2, r3);
                bl[ni * 2][0] = r0; bl[ni * 2][1] = r1;
                bl[ni * 2 + 1][0] = r2; bl[ni * 2 + 1][1] = r3;
            }
            #pragma unroll
            for (int mi = 0; mi < 2; mi++)
                #pragma unroll
                for (int nj = 0; nj < 8; nj++)
                    mma16816(acc[mi][nj], ah[mi], bh[nj]);
            #pragma unroll
            for (int mi = 0; mi < 2; mi++)
                #pragma unroll
                for (int nj = 0; nj < 8; nj++)
                    mma16816(acc[mi][nj], ah[mi], bl[nj]);
            #pragma unroll
            for (int mi = 0; mi < 2; mi++)
                #pragma unroll
                for (int nj = 0; nj < 8; nj++)
                    mma16816(acc[mi][nj], al[mi], bh[nj]);
        }
    }

    #pragma unroll
    for (int mi = 0; mi < 2; mi++) {
        const int row = bm + wm + mi * 16 + (lane >> 2);
        #pragma unroll
        for (int nj = 0; nj < 8; nj++) {
            const int col = bn + wn + nj * 8 + (lane & 3) * 2;
            const float b0 = bias[col], b1 = bias[col + 1];
            float2* c0 = (float2*)(C + (size_t)row * N + col);
            float2* c1 = (float2*)(C + (size_t)(row + 8) * N + col);
            *c0 = make_float2(acc[mi][nj][0] + b0, acc[mi][nj][1] + b1);
            *c1 = make_float2(acc[mi][nj][2] + b0, acc[mi][nj][3] + b1);
        }
    }
}

// ---------------------------------------------------------------------------
// Flash attention (causal), packed fp32x2 math. One thread per query row.
// ---------------------------------------------------------------------------
#define ATT_BM 128
#define ATT_BN 32

__global__ void __launch_bounds__(128)
flash_attn_kernel() {
    const int qblk = blockIdx.x;
    const int bh   = blockIdx.y;
    const int b = bh >> 4, h = bh & 15;
    const int tid = threadIdx.x;
    const int qi = qblk * ATT_BM + tid;

    __shared__ float4 Ks[ATT_BN][16];
    __shared__ float4 Vs[ATT_BN][16];

    // q as 32 packed f32x2 values
    const float* qptr = g_qkv + ((size_t)(b * Ss) + qi) * QKVD + h * HDIM;
    u64t q2[32];
    {
        const ulonglong2* qp = (const ulonglong2*)qptr;
        #pragma unroll
        for (int j = 0; j < 16; j++) {
            ulonglong2 t = qp[j];
            q2[2 * j] = t.x; q2[2 * j + 1] = t.y;
        }
    }

    u64t o2[32];
    #pragma unroll
    for (int j = 0; j < 32; j++) o2[j] = 0ull;   // (0.0f, 0.0f)
    float mrow = -INFINITY, lrow = 0.f;
    const float scale = 0.125f;

    const int ntiles = qblk * 4 + 4;
    const int ldr = tid >> 2;
    const int ldc = (tid & 3) * 4;

    for (int kt = 0; kt < ntiles; kt++) {
        const float* kbase = g_qkv + ((size_t)(b * Ss) + kt * ATT_BN + ldr) * QKVD + Dd + h * HDIM;
        const float* vbase = kbase + Dd;
        #pragma unroll
        for (int u = 0; u < 4; u++) {
            Ks[ldr][ldc + u] = ((const float4*)kbase)[ldc + u];
            Vs[ldr][ldc + u] = ((const float4*)vbase)[ldc + u];
        }
        __syncthreads();

        float sc[ATT_BN];
        #pragma unroll 4
        for (int n = 0; n < ATT_BN; n++) {
            const ulonglong2* kp = (const ulonglong2*)Ks[n];
            u64t a0 = 0ull, a1 = 0ull, a2 = 0ull, a3 = 0ull;
            #pragma unroll
            for (int j = 0; j < 8; j++) {
                ulonglong2 kv0 = kp[2 * j];
                ulonglong2 kv1 = kp[2 * j + 1];
                fma2(a0, q2[4 * j + 0], kv0.x);
                fma2(a1, q2[4 * j + 1], kv0.y);
                fma2(a2, q2[4 * j + 2], kv1.x);
                fma2(a3, q2[4 * j + 3], kv1.y);
            }
            add2(a0, a1); add2(a2, a3); add2(a0, a2);
            float2 dv = unpack2(a0);
            sc[n] = (dv.x + dv.y) * scale;
        }
        if (kt >= qblk * 4) {
            const int kb0 = kt * ATT_BN;
            #pragma unroll
            for (int n = 0; n < ATT_BN; n++)
                if (kb0 + n > qi) sc[n] = -INFINITY;
        }
        float mnew = mrow;
        #pragma unroll
        for (int n = 0; n < ATT_BN; n++) mnew = fmaxf(mnew, sc[n]);
        const float corr = __expf(mrow - mnew);
        lrow *= corr;
        {
            const u64t corr2 = pack2(corr, corr);
            #pragma unroll
            for (int j = 0; j < 32; j++) mul2(o2[j], corr2);
        }
        #pragma unroll
        for (int n = 0; n < ATT_BN; n++) {
            sc[n] = __expf(sc[n] - mnew);
            lrow += sc[n];
        }
        #pragma unroll 2
        for (int n = 0; n < ATT_BN; n++) {
            const u64t pn2 = pack2(sc[n], sc[n]);
            const ulonglong2* vp = (const ulonglong2*)Vs[n];
            #pragma unroll
            for (int j = 0; j < 16; j++) {
                ulonglong2 vv = vp[j];
                fma2(o2[2 * j], pn2, vv.x);
                fma2(o2[2 * j + 1], pn2, vv.y);
            }
        }
        mrow = mnew;
        __syncthreads();
    }

    const float invl = 1.f / lrow;
    const u64t invl2 = pack2(invl, invl);
    #pragma unroll
    for (int j = 0; j < 32; j++) mul2(o2[j], invl2);
    ulonglong2* yout = (ulonglong2*)(g_y + ((size_t)(b * Ss) + qi) * Dd + h * HDIM);
    #pragma unroll
    for (int j = 0; j < 16; j++) {
        ulonglong2 t;
        t.x = o2[2 * j]; t.y = o2[2 * j + 1];
        yout[j] = t;
    }
}

// ---------------------------------------------------------------------------
// Launch
// ---------------------------------------------------------------------------
extern "C" void kernel_launch(void* const* d_in, const int* in_sizes, int n_in,
                              void* d_out, int out_size) {
    const float* x      = (const float*)d_in[0];
    const float* norm_w = (const float*)d_in[1];
    const float* qkv_w  = (const float*)d_in[2];
    const float* qkv_b  = (const float*)d_in[3];
    const float* proj_w = (const float*)d_in[4];
    const float* proj_b = (const float*)d_in[5];
    float* out = (float*)d_out;

    float *p_xn, *p_qkv, *p_y;
    __nv_bfloat16 *p_hA, *p_lA, *p_hW, *p_lW;
    cudaGetSymbolAddress((void**)&p_xn, g_xn);
    cudaGetSymbolAddress((void**)&p_qkv, g_qkv);
    cudaGetSymbolAddress((void**)&p_y, g_y);
    cudaGetSymbolAddress((void**)&p_hA, g_hA);
    cudaGetSymbolAddress((void**)&p_lA, g_lA);
    cudaGetSymbolAddress((void**)&p_hW, g_hW);
    cudaGetSymbolAddress((void**)&p_lW, g_lW);

    cudaFuncSetAttribute(gemm_bf16x3, cudaFuncAttributeMaxDynamicSharedMemorySize, GSMEM);

    // 1) RMSNorm
    rmsnorm_kernel<<<Mrows, 256>>>(x, norm_w);
    // 2) RoPE table
    rope_table_kernel<<<Ss, 32>>>();
    // 3) split xn and qkv_w
    split_bf16_kernel<<<(Mrows * Dd / 4 + 255) / 256, 256>>>(
        (const float4*)p_xn, (uint2*)p_hA, (uint2*)p_lA, Mrows * Dd / 4);
    split_bf16_kernel<<<(QKVD * Dd / 4 + 255) / 256, 256>>>(
        (const float4*)qkv_w, (uint2*)p_hW, (uint2*)p_lW, QKVD * Dd / 4);
    // 4) QKV GEMM
    gemm_bf16x3<<<dim3(QKVD / 128, Mrows / 128), 256, GSMEM>>>(
        p_hA, p_lA, p_hW, p_lW, qkv_b, p_qkv, Mrows, QKVD, Dd);
    // 5) RoPE
    {
        const int total = Bb * Ss * Hh * 32;
        rope_kernel<<<(total + 255) / 256, 256>>>();
    }
    // 6) Flash attention (packed fp32x2)
    flash_attn_kernel<<<dim3(Ss / ATT_BM, Bb * Hh), 128>>>();
    // 7) split y and proj_w
    split_bf16_kernel<<<(Mrows * Dd / 4 + 255) / 256, 256>>>(
        (const float4*)p_y, (uint2*)p_hA, (uint2*)p_lA, Mrows * Dd / 4);
    split_bf16_kernel<<<(Dd * Dd / 4 + 255) / 256, 256>>>(
        (const float4*)proj_w, (uint2*)p_hW, (uint2*)p_lW, Dd * Dd / 4);
    // 8) Output projection
    gemm_bf16x3<<<dim3(Dd / 128, Mrows / 128), 256, GSMEM>>>(
        p_hA, p_lA, p_hW, p_lW, proj_b, out, Mrows, Dd, Dd);

    (void)in_sizes; (void)n_in; (void)out_size;
}

// round 6
// speedup vs baseline: 1.7639x; 1.1507x over previous
#include <cuda_runtime.h>
#include <cuda_fp16.h>
#include <cstdint>
#include <math.h>

#define Bb 2
#define Ss 2048
#define Dd 1024
#define Hh 16
#define HDIM 64
#define Mrows (Bb*Ss)   // 4096
#define QKVD (3*Dd)     // 3072

// ---------------------------------------------------------------------------
// Scratch (static device arrays are permitted)
// ---------------------------------------------------------------------------
__device__ float g_xn[(size_t)Mrows * Dd];
__device__ float g_qkv[(size_t)Mrows * QKVD];
__device__ float g_y[(size_t)Mrows * Dd];
__device__ float g_cos[Ss * 32];
__device__ float g_sin[Ss * 32];
__device__ __half g_hA[(size_t)Mrows * Dd];
__device__ __half g_lA[(size_t)Mrows * Dd];
__device__ __half g_hW[(size_t)QKVD * Dd];

// ---------------------------------------------------------------------------
// Helpers
// ---------------------------------------------------------------------------
typedef unsigned long long u64t;

__device__ __forceinline__ uint32_t smem_to_u32(const void* p) {
    uint32_t a;
    asm("{ .reg .u64 t; cvta.to.shared.u64 t, %1; cvt.u32.u64 %0, t; }"
        : "=r"(a) : "l"(p));
    return a;
}
__device__ __forceinline__ void ldsm_x4(uint32_t addr, uint32_t& r0, uint32_t& r1,
                                        uint32_t& r2, uint32_t& r3) {
    asm volatile("ldmatrix.sync.aligned.m8n8.x4.shared.b16 {%0,%1,%2,%3}, [%4];"
                 : "=r"(r0), "=r"(r1), "=r"(r2), "=r"(r3) : "r"(addr));
}
__device__ __forceinline__ void mma16816(float* c, const uint32_t* a, const uint32_t* b) {
    asm volatile("mma.sync.aligned.m16n8k16.row.col.f32.f16.f16.f32 "
                 "{%0,%1,%2,%3}, {%4,%5,%6,%7}, {%8,%9}, {%0,%1,%2,%3};"
                 : "+f"(c[0]), "+f"(c[1]), "+f"(c[2]), "+f"(c[3])
                 : "r"(a[0]), "r"(a[1]), "r"(a[2]), "r"(a[3]), "r"(b[0]), "r"(b[1]));
}
#define CP_ASYNC16(sa, ga) \
    asm volatile("cp.async.cg.shared.global [%0], [%1], 16;" :: "r"(sa), "l"(ga))
#define CP_COMMIT() asm volatile("cp.async.commit_group;" ::: "memory")
#define CP_WAIT1()  asm volatile("cp.async.wait_group 1;" ::: "memory")

// Packed f32x2 ops (Blackwell base ISA)
__device__ __forceinline__ u64t pack2(float x, float y) {
    u64t r;
    asm("mov.b64 %0, {%1,%2};" : "=l"(r) : "f"(x), "f"(y));
    return r;
}
__device__ __forceinline__ float2 unpack2(u64t v) {
    float2 r;
    asm("mov.b64 {%0,%1}, %2;" : "=f"(r.x), "=f"(r.y) : "l"(v));
    return r;
}
__device__ __forceinline__ void fma2(u64t& d, u64t a, u64t b) {
    asm("fma.rn.f32x2 %0, %1, %2, %0;" : "+l"(d) : "l"(a), "l"(b));
}
__device__ __forceinline__ void mul2(u64t& d, u64t a) {
    asm("mul.rn.f32x2 %0, %0, %1;" : "+l"(d) : "l"(a));
}
__device__ __forceinline__ void add2(u64t& d, u64t a) {
    asm("add.rn.f32x2 %0, %0, %1;" : "+l"(d) : "l"(a));
}

// ---------------------------------------------------------------------------
// RMSNorm
// ---------------------------------------------------------------------------
__global__ void rmsnorm_kernel(const float* __restrict__ x,
                               const float* __restrict__ w) {
    const int row = blockIdx.x;
    const float* xr = x + (size_t)row * Dd;
    float ss = 0.f;
    for (int i = threadIdx.x; i < Dd; i += blockDim.x) {
        float v = xr[i];
        ss += v * v;
    }
    __shared__ float red[32];
    #pragma unroll
    for (int o = 16; o > 0; o >>= 1) ss += __shfl_xor_sync(0xffffffffu, ss, o);
    const int wid = threadIdx.x >> 5, lid = threadIdx.x & 31;
    if (lid == 0) red[wid] = ss;
    __syncthreads();
    if (wid == 0) {
        ss = (lid < (int)(blockDim.x >> 5)) ? red[lid] : 0.f;
        #pragma unroll
        for (int o = 16; o > 0; o >>= 1) ss += __shfl_xor_sync(0xffffffffu, ss, o);
        if (lid == 0) red[0] = ss;
    }
    __syncthreads();
    const float inv = rsqrtf(red[0] * (1.0f / Dd) + 1e-6f);
    float* out = g_xn + (size_t)row * Dd;
    for (int i = threadIdx.x; i < Dd; i += blockDim.x)
        out[i] = xr[i] * inv * w[i];
}

// ---------------------------------------------------------------------------
// RoPE table + apply
// ---------------------------------------------------------------------------
__global__ void rope_table_kernel() {
    const int t = blockIdx.x;
    const int i = threadIdx.x;
    double inv = pow(10000.0, -((double)(2 * i)) / 64.0);
    double a = (double)t * inv;
    g_cos[t * 32 + i] = (float)cos(a);
    g_sin[t * 32 + i] = (float)sin(a);
}

__global__ void rope_kernel() {
    const int idx = blockIdx.x * blockDim.x + threadIdx.x;
    if (idx >= Bb * Ss * Hh * 32) return;
    const int j = idx & 31;
    const int h = (idx >> 5) & (Hh - 1);
    const int s = (idx >> 9) & (Ss - 1);
    const int b = idx >> 20;
    const float c = g_cos[s * 32 + j];
    const float sn = g_sin[s * 32 + j];
    const size_t base = ((size_t)(b * Ss + s)) * QKVD + h * HDIM + j;
    float q1 = g_qkv[base], q2 = g_qkv[base + 32];
    g_qkv[base]      = q1 * c - q2 * sn;
    g_qkv[base + 32] = q2 * c + q1 * sn;
    float k1 = g_qkv[base + Dd], k2 = g_qkv[base + Dd + 32];
    g_qkv[base + Dd]      = k1 * c - k2 * sn;
    g_qkv[base + Dd + 32] = k2 * c + k1 * sn;
}

// ---------------------------------------------------------------------------
// fp32 -> (hi,lo) fp16 split (and hi-only variant for weights)
// ---------------------------------------------------------------------------
__device__ __forceinline__ uint32_t packh(__half a, __half b) {
    return ((uint32_t)__half_as_ushort(b) << 16) | (uint32_t)__half_as_ushort(a);
}
__global__ void split_f16_kernel(const float4* __restrict__ src,
                                 uint2* __restrict__ hi, uint2* __restrict__ lo, int n4) {
    int i = blockIdx.x * blockDim.x + threadIdx.x;
    if (i >= n4) return;
    float4 v = src[i];
    __half h0 = __float2half_rn(v.x);
    __half h1 = __float2half_rn(v.y);
    __half h2 = __float2half_rn(v.z);
    __half h3 = __float2half_rn(v.w);
    __half l0 = __float2half_rn(v.x - __half2float(h0));
    __half l1 = __float2half_rn(v.y - __half2float(h1));
    __half l2 = __float2half_rn(v.z - __half2float(h2));
    __half l3 = __float2half_rn(v.w - __half2float(h3));
    hi[i] = make_uint2(packh(h0, h1), packh(h2, h3));
    lo[i] = make_uint2(packh(l0, l1), packh(l2, l3));
}
__global__ void split_f16_hi_kernel(const float4* __restrict__ src,
                                    uint2* __restrict__ hi, int n4) {
    int i = blockIdx.x * blockDim.x + threadIdx.x;
    if (i >= n4) return;
    float4 v = src[i];
    hi[i] = make_uint2(packh(__float2half_rn(v.x), __float2half_rn(v.y)),
                       packh(__float2half_rn(v.z), __float2half_rn(v.w)));
}

// ---------------------------------------------------------------------------
// Split-precision GEMM via mma.sync fp16, 2 passes:
//   C = (Ahi + Alo) * Whi^T + bias    (error ~ A*Wlo ~ 2^-11 relative)
//   CTA 128x128, 8 warps, KC=32, 3-stage cp.async pipeline, 3 tiles/stage.
// ---------------------------------------------------------------------------
#define PADB  80
#define TILEB (128 * PADB)           // 10240
#define STAGEB (3 * TILEB)           // 30720: Ah, Al, Wh
#define NSTAGE 3
#define GSMEM (NSTAGE * STAGEB)      // 92160

__global__ void __launch_bounds__(256)
gemm_f16x2(const __half* __restrict__ Ahi, const __half* __restrict__ Alo,
           const __half* __restrict__ Whi,
           const float* __restrict__ bias, float* __restrict__ C,
           int M, int N, int K) {
    extern __shared__ char smem[];
    const uint32_t sb = smem_to_u32(smem);
    const int tid = threadIdx.x, lane = tid & 31, w = tid >> 5;
    const int bm = blockIdx.y * 128, bn = blockIdx.x * 128;
    const int wm = (w >> 1) * 32, wn = (w & 1) * 64;

    const __half* srcs[3] = {Ahi, Alo, Whi};
    const int rb[3] = {bm, bm, bn};

    auto load_stage = [&](int s, int k0) {
        const uint32_t st = sb + s * STAGEB;
        #pragma unroll
        for (int t = 0; t < 3; t++) {
            const __half* src = srcs[t] + (size_t)rb[t] * K + k0;
            const uint32_t tb = st + t * TILEB;
            #pragma unroll
            for (int j = 0; j < 2; j++) {
                const int c = tid + j * 256;
                const int row = c >> 2, c16 = c & 3;
                const uint32_t sa = tb + row * PADB + c16 * 16;
                const __half* ga = src + (size_t)row * K + c16 * 8;
                CP_ASYNC16(sa, ga);
            }
        }
    };

    float acc[2][8][4];
    #pragma unroll
    for (int mi = 0; mi < 2; mi++)
        #pragma unroll
        for (int nj = 0; nj < 8; nj++)
            #pragma unroll
            for (int r = 0; r < 4; r++) acc[mi][nj][r] = 0.f;

    load_stage(0, 0);  CP_COMMIT();
    load_stage(1, 32); CP_COMMIT();

    const int nch = K >> 5;
    const int sel = lane >> 3;
    const int asub = (sel & 1) * 8, ak8 = (sel >> 1) * 8;
    const int nsub = (sel >> 1) * 8, bk8 = (sel & 1) * 8;

    for (int cidx = 0; cidx < nch; cidx++) {
        CP_WAIT1();
        __syncthreads();
        if (cidx + 2 < nch) load_stage((cidx + 2) % NSTAGE, (cidx + 2) * 32);
        CP_COMMIT();

        const uint32_t st = sb + (cidx % NSTAGE) * STAGEB;
        #pragma unroll
        for (int kk = 0; kk < 2; kk++) {
            const int ko = kk * 16;
            uint32_t ah[2][4], al[2][4], wh[8][2];
            #pragma unroll
            for (int mi = 0; mi < 2; mi++) {
                const uint32_t addr = st + (wm + mi * 16 + (lane & 7) + asub) * PADB
                                      + (ko + ak8) * 2;
                ldsm_x4(addr, ah[mi][0], ah[mi][1], ah[mi][2], ah[mi][3]);
                ldsm_x4(addr + TILEB, al[mi][0], al[mi][1], al[mi][2], al[mi][3]);
            }
            #pragma unroll
            for (int ni = 0; ni < 4; ni++) {
                const uint32_t addr = st + 2 * TILEB
                                      + (wn + ni * 16 + (lane & 7) + nsub) * PADB
                                      + (ko + bk8) * 2;
                uint32_t r0, r1, r2, r3;
                ldsm_x4(addr, r0, r1, r2, r3);
                wh[ni * 2][0] = r0; wh[ni * 2][1] = r1;
                wh[ni * 2 + 1][0] = r2; wh[ni * 2 + 1][1] = r3;
            }
            // Pass-outermost: 16 independent accumulators between reuses.
            #pragma unroll
            for (int mi = 0; mi < 2; mi++)
                #pragma unroll
                for (int nj = 0; nj < 8; nj++)
                    mma16816(acc[mi][nj], ah[mi], wh[nj]);
            #pragma unroll
            for (int mi = 0; mi < 2; mi++)
                #pragma unroll
                for (int nj = 0; nj < 8; nj++)
                    mma16816(acc[mi][nj], al[mi], wh[nj]);
        }
    }

    #pragma unroll
    for (int mi = 0; mi < 2; mi++) {
        const int row = bm + wm + mi * 16 + (lane >> 2);
        #pragma unroll
        for (int nj = 0; nj < 8; nj++) {
            const int col = bn + wn + nj * 8 + (lane & 3) * 2;
            const float b0 = bias[col], b1 = bias[col + 1];
            float2* c0 = (float2*)(C + (size_t)row * N + col);
            float2* c1 = (float2*)(C + (size_t)(row + 8) * N + col);
            *c0 = make_float2(acc[mi][nj][0] + b0, acc[mi][nj][1] + b1);
            *c1 = make_float2(acc[mi][nj][2] + b0, acc[mi][nj][3] + b1);
        }
    }
}

// ---------------------------------------------------------------------------
// Flash attention (causal), packed fp32x2 math. One thread per query row.
// ---------------------------------------------------------------------------
#define ATT_BM 128
#define ATT_BN 32

__global__ void __launch_bounds__(128)
flash_attn_kernel() {
    const int qblk = blockIdx.x;
    const int bh   = blockIdx.y;
    const int b = bh >> 4, h = bh & 15;
    const int tid = threadIdx.x;
    const int qi = qblk * ATT_BM + tid;

    __shared__ float4 Ks[ATT_BN][16];
    __shared__ float4 Vs[ATT_BN][16];

    const float* qptr = g_qkv + ((size_t)(b * Ss) + qi) * QKVD + h * HDIM;
    u64t q2[32];
    {
        const ulonglong2* qp = (const ulonglong2*)qptr;
        #pragma unroll
        for (int j = 0; j < 16; j++) {
            ulonglong2 t = qp[j];
            q2[2 * j] = t.x; q2[2 * j + 1] = t.y;
        }
    }

    u64t o2[32];
    #pragma unroll
    for (int j = 0; j < 32; j++) o2[j] = 0ull;
    float mrow = -INFINITY, lrow = 0.f;
    const float scale = 0.125f;

    const int ntiles = qblk * 4 + 4;
    const int ldr = tid >> 2;
    const int ldc = (tid & 3) * 4;

    for (int kt = 0; kt < ntiles; kt++) {
        const float* kbase = g_qkv + ((size_t)(b * Ss) + kt * ATT_BN + ldr) * QKVD + Dd + h * HDIM;
        const float* vbase = kbase + Dd;
        #pragma unroll
        for (int u = 0; u < 4; u++) {
            Ks[ldr][ldc + u] = ((const float4*)kbase)[ldc + u];
            Vs[ldr][ldc + u] = ((const float4*)vbase)[ldc + u];
        }
        __syncthreads();

        float sc[ATT_BN];
        #pragma unroll 4
        for (int n = 0; n < ATT_BN; n++) {
            const ulonglong2* kp = (const ulonglong2*)Ks[n];
            u64t a0 = 0ull, a1 = 0ull, a2 = 0ull, a3 = 0ull;
            #pragma unroll
            for (int j = 0; j < 8; j++) {
                ulonglong2 kv0 = kp[2 * j];
                ulonglong2 kv1 = kp[2 * j + 1];
                fma2(a0, q2[4 * j + 0], kv0.x);
                fma2(a1, q2[4 * j + 1], kv0.y);
                fma2(a2, q2[4 * j + 2], kv1.x);
                fma2(a3, q2[4 * j + 3], kv1.y);
            }
            add2(a0, a1); add2(a2, a3); add2(a0, a2);
            float2 dv = unpack2(a0);
            sc[n] = (dv.x + dv.y) * scale;
        }
        if (kt >= qblk * 4) {
            const int kb0 = kt * ATT_BN;
            #pragma unroll
            for (int n = 0; n < ATT_BN; n++)
                if (kb0 + n > qi) sc[n] = -INFINITY;
        }
        float mnew = mrow;
        #pragma unroll
        for (int n = 0; n < ATT_BN; n++) mnew = fmaxf(mnew, sc[n]);
        const float corr = __expf(mrow - mnew);
        lrow *= corr;
        {
            const u64t corr2 = pack2(corr, corr);
            #pragma unroll
            for (int j = 0; j < 32; j++) mul2(o2[j], corr2);
        }
        #pragma unroll
        for (int n = 0; n < ATT_BN; n++) {
            sc[n] = __expf(sc[n] - mnew);
            lrow += sc[n];
        }
        #pragma unroll 2
        for (int n = 0; n < ATT_BN; n++) {
            const u64t pn2 = pack2(sc[n], sc[n]);
            const ulonglong2* vp = (const ulonglong2*)Vs[n];
            #pragma unroll
            for (int j = 0; j < 16; j++) {
                ulonglong2 vv = vp[j];
                fma2(o2[2 * j], pn2, vv.x);
                fma2(o2[2 * j + 1], pn2, vv.y);
            }
        }
        mrow = mnew;
        __syncthreads();
    }

    const float invl = 1.f / lrow;
    const u64t invl2 = pack2(invl, invl);
    #pragma unroll
    for (int j = 0; j < 32; j++) mul2(o2[j], invl2);
    ulonglong2* yout = (ulonglong2*)(g_y + ((size_t)(b * Ss) + qi) * Dd + h * HDIM);
    #pragma unroll
    for (int j = 0; j < 16; j++) {
        ulonglong2 t;
        t.x = o2[2 * j]; t.y = o2[2 * j + 1];
        yout[j] = t;
    }
}

// ---------------------------------------------------------------------------
// Launch
// ---------------------------------------------------------------------------
extern "C" void kernel_launch(void* const* d_in, const int* in_sizes, int n_in,
                              void* d_out, int out_size) {
    const float* x      = (const float*)d_in[0];
    const float* norm_w = (const float*)d_in[1];
    const float* qkv_w  = (const float*)d_in[2];
    const float* qkv_b  = (const float*)d_in[3];
    const float* proj_w = (const float*)d_in[4];
    const float* proj_b = (const float*)d_in[5];
    float* out = (float*)d_out;

    float *p_xn, *p_qkv, *p_y;
    __half *p_hA, *p_lA, *p_hW;
    cudaGetSymbolAddress((void**)&p_xn, g_xn);
    cudaGetSymbolAddress((void**)&p_qkv, g_qkv);
    cudaGetSymbolAddress((void**)&p_y, g_y);
    cudaGetSymbolAddress((void**)&p_hA, g_hA);
    cudaGetSymbolAddress((void**)&p_lA, g_lA);
    cudaGetSymbolAddress((void**)&p_hW, g_hW);

    cudaFuncSetAttribute(gemm_f16x2, cudaFuncAttributeMaxDynamicSharedMemorySize, GSMEM);

    // 1) RMSNorm
    rmsnorm_kernel<<<Mrows, 256>>>(x, norm_w);
    // 2) RoPE table
    rope_table_kernel<<<Ss, 32>>>();
    // 3) split xn (hi+lo) and qkv_w (hi only)
    split_f16_kernel<<<(Mrows * Dd / 4 + 255) / 256, 256>>>(
        (const float4*)p_xn, (uint2*)p_hA, (uint2*)p_lA, Mrows * Dd / 4);
    split_f16_hi_kernel<<<(QKVD * Dd / 4 + 255) / 256, 256>>>(
        (const float4*)qkv_w, (uint2*)p_hW, QKVD * Dd / 4);
    // 4) QKV GEMM (fp16 2-pass)
    gemm_f16x2<<<dim3(QKVD / 128, Mrows / 128), 256, GSMEM>>>(
        p_hA, p_lA, p_hW, qkv_b, p_qkv, Mrows, QKVD, Dd);
    // 5) RoPE
    {
        const int total = Bb * Ss * Hh * 32;
        rope_kernel<<<(total + 255) / 256, 256>>>();
    }
    // 6) Flash attention (packed fp32x2)
    flash_attn_kernel<<<dim3(Ss / ATT_BM, Bb * Hh), 128>>>();
    // 7) split y (hi+lo) and proj_w (hi only)
    split_f16_kernel<<<(Mrows * Dd / 4 + 255) / 256, 256>>>(
        (const float4*)p_y, (uint2*)p_hA, (uint2*)p_lA, Mrows * Dd / 4);
    split_f16_hi_kernel<<<(Dd * Dd / 4 + 255) / 256, 256>>>(
        (const float4*)proj_w, (uint2*)p_hW, Dd * Dd / 4);
    // 8) Output projection (fp16 2-pass)
    gemm_f16x2<<<dim3(Dd / 128, Mrows / 128), 256, GSMEM>>>(
        p_hA, p_lA, p_hW, proj_b, out, Mrows, Dd, Dd);

    (void)in_sizes; (void)n_in; (void)out_size;
}

// round 7
// speedup vs baseline: 5.5053x; 3.1212x over previous
#include <cuda_runtime.h>
#include <cuda_fp16.h>
#include <cstdint>
#include <math.h>

#define Bb 2
#define Ss 2048
#define Dd 1024
#define Hh 16
#define HDIM 64
#define Mrows (Bb*Ss)   // 4096
#define QKVD (3*Dd)     // 3072

// ---------------------------------------------------------------------------
// Scratch
// ---------------------------------------------------------------------------
__device__ float g_xn[(size_t)Mrows * Dd];
__device__ float g_qkv[(size_t)Mrows * QKVD];
__device__ float g_y[(size_t)Mrows * Dd];
__device__ float g_cos[Ss * 32];
__device__ float g_sin[Ss * 32];
__device__ __half g_hA[(size_t)Mrows * Dd];
__device__ __half g_lA[(size_t)Mrows * Dd];
__device__ __half g_hW[(size_t)QKVD * Dd];
// head-major fp16 q/k/v for attention: [b*16+h][s][64]
__device__ __half g_qh[(size_t)Bb * Hh * Ss * HDIM];
__device__ __half g_kh[(size_t)Bb * Hh * Ss * HDIM];
__device__ __half g_vh[(size_t)Bb * Hh * Ss * HDIM];

// ---------------------------------------------------------------------------
// Helpers
// ---------------------------------------------------------------------------
__device__ __forceinline__ uint32_t smem_to_u32(const void* p) {
    uint32_t a;
    asm("{ .reg .u64 t; cvta.to.shared.u64 t, %1; cvt.u32.u64 %0, t; }"
        : "=r"(a) : "l"(p));
    return a;
}
__device__ __forceinline__ void ldsm_x4(uint32_t addr, uint32_t& r0, uint32_t& r1,
                                        uint32_t& r2, uint32_t& r3) {
    asm volatile("ldmatrix.sync.aligned.m8n8.x4.shared.b16 {%0,%1,%2,%3}, [%4];"
                 : "=r"(r0), "=r"(r1), "=r"(r2), "=r"(r3) : "r"(addr));
}
__device__ __forceinline__ void ldsm_x4t(uint32_t addr, uint32_t& r0, uint32_t& r1,
                                         uint32_t& r2, uint32_t& r3) {
    asm volatile("ldmatrix.sync.aligned.m8n8.x4.trans.shared.b16 {%0,%1,%2,%3}, [%4];"
                 : "=r"(r0), "=r"(r1), "=r"(r2), "=r"(r3) : "r"(addr));
}
__device__ __forceinline__ void mma16816(float* c, const uint32_t* a, const uint32_t* b) {
    asm volatile("mma.sync.aligned.m16n8k16.row.col.f32.f16.f16.f32 "
                 "{%0,%1,%2,%3}, {%4,%5,%6,%7}, {%8,%9}, {%0,%1,%2,%3};"
                 : "+f"(c[0]), "+f"(c[1]), "+f"(c[2]), "+f"(c[3])
                 : "r"(a[0]), "r"(a[1]), "r"(a[2]), "r"(a[3]), "r"(b[0]), "r"(b[1]));
}
#define CP_ASYNC16(sa, ga) \
    asm volatile("cp.async.cg.shared.global [%0], [%1], 16;" :: "r"(sa), "l"(ga))
#define CP_COMMIT() asm volatile("cp.async.commit_group;" ::: "memory")
#define CP_WAIT1()  asm volatile("cp.async.wait_group 1;" ::: "memory")
#define CP_WAIT0()  asm volatile("cp.async.wait_group 0;" ::: "memory")

__device__ __forceinline__ uint32_t packf2h(float a, float b) {
    __half2 h = __floats2half2_rn(a, b);
    return *(uint32_t*)&h;
}

// ---------------------------------------------------------------------------
// RMSNorm
// ---------------------------------------------------------------------------
__global__ void rmsnorm_kernel(const float* __restrict__ x,
                               const float* __restrict__ w) {
    const int row = blockIdx.x;
    const float* xr = x + (size_t)row * Dd;
    float ss = 0.f;
    for (int i = threadIdx.x; i < Dd; i += blockDim.x) {
        float v = xr[i];
        ss += v * v;
    }
    __shared__ float red[32];
    #pragma unroll
    for (int o = 16; o > 0; o >>= 1) ss += __shfl_xor_sync(0xffffffffu, ss, o);
    const int wid = threadIdx.x >> 5, lid = threadIdx.x & 31;
    if (lid == 0) red[wid] = ss;
    __syncthreads();
    if (wid == 0) {
        ss = (lid < (int)(blockDim.x >> 5)) ? red[lid] : 0.f;
        #pragma unroll
        for (int o = 16; o > 0; o >>= 1) ss += __shfl_xor_sync(0xffffffffu, ss, o);
        if (lid == 0) red[0] = ss;
    }
    __syncthreads();
    const float inv = rsqrtf(red[0] * (1.0f / Dd) + 1e-6f);
    float* out = g_xn + (size_t)row * Dd;
    for (int i = threadIdx.x; i < Dd; i += blockDim.x)
        out[i] = xr[i] * inv * w[i];
}

// ---------------------------------------------------------------------------
// RoPE table
// ---------------------------------------------------------------------------
__global__ void rope_table_kernel() {
    const int t = blockIdx.x;
    const int i = threadIdx.x;
    double inv = pow(10000.0, -((double)(2 * i)) / 64.0);
    double a = (double)t * inv;
    g_cos[t * 32 + i] = (float)cos(a);
    g_sin[t * 32 + i] = (float)sin(a);
}

// ---------------------------------------------------------------------------
// Fused RoPE + fp16 convert + head-major transpose for q,k,v
// q is pre-scaled by 1/sqrt(HDIM) = 0.125
// ---------------------------------------------------------------------------
__global__ void rope_cvt_kernel() {
    const int idx = blockIdx.x * blockDim.x + threadIdx.x;
    if (idx >= Bb * Ss * Hh * 32) return;
    const int j = idx & 31;
    const int h = (idx >> 5) & (Hh - 1);
    const int s = (idx >> 9) & (Ss - 1);
    const int b = idx >> 20;
    const float c = g_cos[s * 32 + j];
    const float sn = g_sin[s * 32 + j];
    const size_t base = ((size_t)(b * Ss + s)) * QKVD + h * HDIM + j;
    const size_t ob = ((size_t)(b * Hh + h) * Ss + s) * HDIM + j;
    float q1 = g_qkv[base], q2 = g_qkv[base + 32];
    g_qh[ob]      = __float2half_rn((q1 * c - q2 * sn) * 0.125f);
    g_qh[ob + 32] = __float2half_rn((q2 * c + q1 * sn) * 0.125f);
    float k1 = g_qkv[base + Dd], k2 = g_qkv[base + Dd + 32];
    g_kh[ob]      = __float2half_rn(k1 * c - k2 * sn);
    g_kh[ob + 32] = __float2half_rn(k2 * c + k1 * sn);
    g_vh[ob]      = __float2half_rn(g_qkv[base + 2 * Dd]);
    g_vh[ob + 32] = __float2half_rn(g_qkv[base + 2 * Dd + 32]);
}

// ---------------------------------------------------------------------------
// fp32 -> (hi,lo) fp16 split (and hi-only for weights)
// ---------------------------------------------------------------------------
__device__ __forceinline__ uint32_t packh(__half a, __half b) {
    return ((uint32_t)__half_as_ushort(b) << 16) | (uint32_t)__half_as_ushort(a);
}
__global__ void split_f16_kernel(const float4* __restrict__ src,
                                 uint2* __restrict__ hi, uint2* __restrict__ lo, int n4) {
    int i = blockIdx.x * blockDim.x + threadIdx.x;
    if (i >= n4) return;
    float4 v = src[i];
    __half h0 = __float2half_rn(v.x);
    __half h1 = __float2half_rn(v.y);
    __half h2 = __float2half_rn(v.z);
    __half h3 = __float2half_rn(v.w);
    __half l0 = __float2half_rn(v.x - __half2float(h0));
    __half l1 = __float2half_rn(v.y - __half2float(h1));
    __half l2 = __float2half_rn(v.z - __half2float(h2));
    __half l3 = __float2half_rn(v.w - __half2float(h3));
    hi[i] = make_uint2(packh(h0, h1), packh(h2, h3));
    lo[i] = make_uint2(packh(l0, l1), packh(l2, l3));
}
__global__ void split_f16_hi_kernel(const float4* __restrict__ src,
                                    uint2* __restrict__ hi, int n4) {
    int i = blockIdx.x * blockDim.x + threadIdx.x;
    if (i >= n4) return;
    float4 v = src[i];
    hi[i] = make_uint2(packh(__float2half_rn(v.x), __float2half_rn(v.y)),
                       packh(__float2half_rn(v.z), __float2half_rn(v.w)));
}

// ---------------------------------------------------------------------------
// Split-precision GEMM via mma.sync fp16, 2 passes (unchanged from R6)
// ---------------------------------------------------------------------------
#define PADB  80
#define TILEB (128 * PADB)
#define STAGEB (3 * TILEB)
#define NSTAGE 3
#define GSMEM (NSTAGE * STAGEB)

__global__ void __launch_bounds__(256)
gemm_f16x2(const __half* __restrict__ Ahi, const __half* __restrict__ Alo,
           const __half* __restrict__ Whi,
           const float* __restrict__ bias, float* __restrict__ C,
           int M, int N, int K) {
    extern __shared__ char smem[];
    const uint32_t sb = smem_to_u32(smem);
    const int tid = threadIdx.x, lane = tid & 31, w = tid >> 5;
    const int bm = blockIdx.y * 128, bn = blockIdx.x * 128;
    const int wm = (w >> 1) * 32, wn = (w & 1) * 64;

    const __half* srcs[3] = {Ahi, Alo, Whi};
    const int rb[3] = {bm, bm, bn};

    auto load_stage = [&](int s, int k0) {
        const uint32_t st = sb + s * STAGEB;
        #pragma unroll
        for (int t = 0; t < 3; t++) {
            const __half* src = srcs[t] + (size_t)rb[t] * K + k0;
            const uint32_t tb = st + t * TILEB;
            #pragma unroll
            for (int j = 0; j < 2; j++) {
                const int c = tid + j * 256;
                const int row = c >> 2, c16 = c & 3;
                const uint32_t sa = tb + row * PADB + c16 * 16;
                const __half* ga = src + (size_t)row * K + c16 * 8;
                CP_ASYNC16(sa, ga);
            }
        }
    };

    float acc[2][8][4];
    #pragma unroll
    for (int mi = 0; mi < 2; mi++)
        #pragma unroll
        for (int nj = 0; nj < 8; nj++)
            #pragma unroll
            for (int r = 0; r < 4; r++) acc[mi][nj][r] = 0.f;

    load_stage(0, 0);  CP_COMMIT();
    load_stage(1, 32); CP_COMMIT();

    const int nch = K >> 5;
    const int sel = lane >> 3;
    const int asub = (sel & 1) * 8, ak8 = (sel >> 1) * 8;
    const int nsub = (sel >> 1) * 8, bk8 = (sel & 1) * 8;

    for (int cidx = 0; cidx < nch; cidx++) {
        CP_WAIT1();
        __syncthreads();
        if (cidx + 2 < nch) load_stage((cidx + 2) % NSTAGE, (cidx + 2) * 32);
        CP_COMMIT();

        const uint32_t st = sb + (cidx % NSTAGE) * STAGEB;
        #pragma unroll
        for (int kk = 0; kk < 2; kk++) {
            const int ko = kk * 16;
            uint32_t ah[2][4], al[2][4], wh[8][2];
            #pragma unroll
            for (int mi = 0; mi < 2; mi++) {
                const uint32_t addr = st + (wm + mi * 16 + (lane & 7) + asub) * PADB
                                      + (ko + ak8) * 2;
                ldsm_x4(addr, ah[mi][0], ah[mi][1], ah[mi][2], ah[mi][3]);
                ldsm_x4(addr + TILEB, al[mi][0], al[mi][1], al[mi][2], al[mi][3]);
            }
            #pragma unroll
            for (int ni = 0; ni < 4; ni++) {
                const uint32_t addr = st + 2 * TILEB
                                      + (wn + ni * 16 + (lane & 7) + nsub) * PADB
                                      + (ko + bk8) * 2;
                uint32_t r0, r1, r2, r3;
                ldsm_x4(addr, r0, r1, r2, r3);
                wh[ni * 2][0] = r0; wh[ni * 2][1] = r1;
                wh[ni * 2 + 1][0] = r2; wh[ni * 2 + 1][1] = r3;
            }
            #pragma unroll
            for (int mi = 0; mi < 2; mi++)
                #pragma unroll
                for (int nj = 0; nj < 8; nj++)
                    mma16816(acc[mi][nj], ah[mi], wh[nj]);
            #pragma unroll
            for (int mi = 0; mi < 2; mi++)
                #pragma unroll
                for (int nj = 0; nj < 8; nj++)
                    mma16816(acc[mi][nj], al[mi], wh[nj]);
        }
    }

    #pragma unroll
    for (int mi = 0; mi < 2; mi++) {
        const int row = bm + wm + mi * 16 + (lane >> 2);
        #pragma unroll
        for (int nj = 0; nj < 8; nj++) {
            const int col = bn + wn + nj * 8 + (lane & 3) * 2;
            const float b0 = bias[col], b1 = bias[col + 1];
            float2* c0 = (float2*)(C + (size_t)row * N + col);
            float2* c1 = (float2*)(C + (size_t)(row + 8) * N + col);
            *c0 = make_float2(acc[mi][nj][0] + b0, acc[mi][nj][1] + b1);
            *c1 = make_float2(acc[mi][nj][2] + b0, acc[mi][nj][3] + b1);
        }
    }
}

// ---------------------------------------------------------------------------
// Tensor-core flash attention (causal).
// CTA: 64 q-rows x one (b,h). 4 warps, each m16. K/V tiles of 64 keys,
// double-buffered cp.async. Q*K^T and P*V via mma.sync fp16.
// ---------------------------------------------------------------------------
#define FROWH 72                 // halfs per smem row
#define FROWB (FROWH * 2)        // 144 bytes
#define FTILE (64 * FROWB)       // 9216 bytes

__global__ void __launch_bounds__(128)
flash_mma_kernel() {
    __shared__ __align__(16) char fsm[5 * FTILE];   // Q | K0 | K1 | V0 | V1
    const int qblk = blockIdx.x, bh = blockIdx.y;
    const int tid = threadIdx.x, lane = tid & 31, w = tid >> 5;
    const int qbase = qblk * 64, wm = w * 16;
    const uint32_t sq = smem_to_u32(fsm);
    const uint32_t sk0 = sq + FTILE, sk1 = sq + 2 * FTILE;
    const uint32_t sv0 = sq + 3 * FTILE, sv1 = sq + 4 * FTILE;

    const size_t hb = (size_t)bh * Ss * HDIM;

    // Q tile loads (part of group 0)
    {
        const __half* qsrc = g_qh + hb + (size_t)qbase * HDIM;
        #pragma unroll
        for (int i = 0; i < 4; i++) {
            const int c = tid + i * 128;
            const int row = c >> 3, col = (c & 7) * 8;
            CP_ASYNC16(sq + row * FROWB + col * 2, qsrc + row * HDIM + col);
        }
    }
    auto fetch_kv = [&](int kt) {
        const __half* ksrc = g_kh + hb + (size_t)(kt * 64) * HDIM;
        const __half* vsrc = g_vh + hb + (size_t)(kt * 64) * HDIM;
        const uint32_t kb = (kt & 1) ? sk1 : sk0;
        const uint32_t vb = (kt & 1) ? sv1 : sv0;
        #pragma unroll
        for (int i = 0; i < 4; i++) {
            const int c = tid + i * 128;
            const int row = c >> 3, col = (c & 7) * 8;
            CP_ASYNC16(kb + row * FROWB + col * 2, ksrc + row * HDIM + col);
            CP_ASYNC16(vb + row * FROWB + col * 2, vsrc + row * HDIM + col);
        }
    };
    const int nt = qblk + 1;
    fetch_kv(0); CP_COMMIT();
    if (nt > 1) { fetch_kv(1); CP_COMMIT(); }

    uint32_t qf[4][4];
    float o[8][4];
    #pragma unroll
    for (int nj = 0; nj < 8; nj++)
        #pragma unroll
        for (int r = 0; r < 4; r++) o[nj][r] = 0.f;
    float mrow0 = -INFINITY, mrow1 = -INFINITY, lrow0 = 0.f, lrow1 = 0.f;

    for (int kt = 0; kt < nt; kt++) {
        if (kt + 1 < nt) {
            if (kt) { fetch_kv(kt + 1); CP_COMMIT(); }
            CP_WAIT1();
        } else {
            CP_WAIT0();
        }
        __syncthreads();

        if (kt == 0) {
            // load Q a-fragments once
            #pragma unroll
            for (int ks = 0; ks < 4; ks++) {
                const uint32_t addr = sq + (wm + (lane & 15)) * FROWB
                                      + (ks * 16 + (lane >> 4) * 8) * 2;
                ldsm_x4(addr, qf[ks][0], qf[ks][1], qf[ks][2], qf[ks][3]);
            }
        }

        const uint32_t kb = (kt & 1) ? sk1 : sk0;
        const uint32_t vb = (kt & 1) ? sv1 : sv0;

        // S = Q * K^T  (8 n8 tiles of keys)
        float s[8][4];
        #pragma unroll
        for (int nj = 0; nj < 8; nj++)
            #pragma unroll
            for (int r = 0; r < 4; r++) s[nj][r] = 0.f;
        const int sel = lane >> 3;
        #pragma unroll
        for (int ks = 0; ks < 4; ks++) {
            #pragma unroll
            for (int np = 0; np < 4; np++) {
                const uint32_t addr = kb
                    + (np * 16 + (lane & 7) + (sel >> 1) * 8) * FROWB
                    + (ks * 16 + (sel & 1) * 8) * 2;
                uint32_t r0, r1, r2, r3;
                ldsm_x4(addr, r0, r1, r2, r3);
                uint32_t b0[2] = {r0, r1}, b1[2] = {r2, r3};
                mma16816(s[np * 2], qf[ks], b0);
                mma16816(s[np * 2 + 1], qf[ks], b1);
            }
        }

        // causal mask on the diagonal tile
        if (kt == qblk) {
            const int lr0 = wm + (lane >> 2), lr1 = lr0 + 8;
            #pragma unroll
            for (int nj = 0; nj < 8; nj++) {
                const int ck = nj * 8 + 2 * (lane & 3);
                if (ck > lr0)     s[nj][0] = -INFINITY;
                if (ck + 1 > lr0) s[nj][1] = -INFINITY;
                if (ck > lr1)     s[nj][2] = -INFINITY;
                if (ck + 1 > lr1) s[nj][3] = -INFINITY;
            }
        }

        // online softmax
        float mx0 = -INFINITY, mx1 = -INFINITY;
        #pragma unroll
        for (int nj = 0; nj < 8; nj++) {
            mx0 = fmaxf(mx0, fmaxf(s[nj][0], s[nj][1]));
            mx1 = fmaxf(mx1, fmaxf(s[nj][2], s[nj][3]));
        }
        mx0 = fmaxf(mx0, __shfl_xor_sync(0xffffffffu, mx0, 1));
        mx0 = fmaxf(mx0, __shfl_xor_sync(0xffffffffu, mx0, 2));
        mx1 = fmaxf(mx1, __shfl_xor_sync(0xffffffffu, mx1, 1));
        mx1 = fmaxf(mx1, __shfl_xor_sync(0xffffffffu, mx1, 2));
        const float mn0 = fmaxf(mrow0, mx0), mn1 = fmaxf(mrow1, mx1);
        const float c0 = __expf(mrow0 - mn0), c1 = __expf(mrow1 - mn1);
        float sum0 = 0.f, sum1 = 0.f;
        #pragma unroll
        for (int nj = 0; nj < 8; nj++) {
            s[nj][0] = __expf(s[nj][0] - mn0);
            s[nj][1] = __expf(s[nj][1] - mn0);
            s[nj][2] = __expf(s[nj][2] - mn1);
            s[nj][3] = __expf(s[nj][3] - mn1);
            sum0 += s[nj][0] + s[nj][1];
            sum1 += s[nj][2] + s[nj][3];
        }
        sum0 += __shfl_xor_sync(0xffffffffu, sum0, 1);
        sum0 += __shfl_xor_sync(0xffffffffu, sum0, 2);
        sum1 += __shfl_xor_sync(0xffffffffu, sum1, 1);
        sum1 += __shfl_xor_sync(0xffffffffu, sum1, 2);
        lrow0 = lrow0 * c0 + sum0;
        lrow1 = lrow1 * c1 + sum1;
        #pragma unroll
        for (int nj = 0; nj < 8; nj++) {
            o[nj][0] *= c0; o[nj][1] *= c0;
            o[nj][2] *= c1; o[nj][3] *= c1;
        }
        mrow0 = mn0; mrow1 = mn1;

        // O += P * V
        #pragma unroll
        for (int ks = 0; ks < 4; ks++) {
            uint32_t a[4];
            a[0] = packf2h(s[2 * ks][0], s[2 * ks][1]);
            a[1] = packf2h(s[2 * ks][2], s[2 * ks][3]);
            a[2] = packf2h(s[2 * ks + 1][0], s[2 * ks + 1][1]);
            a[3] = packf2h(s[2 * ks + 1][2], s[2 * ks + 1][3]);
            #pragma unroll
            for (int np = 0; np < 4; np++) {
                const uint32_t addr = vb
                    + (ks * 16 + (lane & 7) + (lane & 8)) * FROWB
                    + (np * 16 + ((lane >> 4) & 1) * 8) * 2;
                uint32_t r0, r1, r2, r3;
                ldsm_x4t(addr, r0, r1, r2, r3);
                uint32_t b0[2] = {r0, r1}, b1[2] = {r2, r3};
                mma16816(o[np * 2], a, b0);
                mma16816(o[np * 2 + 1], a, b1);
            }
        }
        __syncthreads();
    }

    // epilogue
    const float inv0 = 1.f / lrow0, inv1 = 1.f / lrow1;
    const int b = bh >> 4, h = bh & 15;
    const int row0 = qbase + wm + (lane >> 2);
    float* y0 = g_y + ((size_t)(b * Ss + row0)) * Dd + h * HDIM;
    float* y1 = y0 + (size_t)8 * Dd;
    #pragma unroll
    for (int nj = 0; nj < 8; nj++) {
        const int col = nj * 8 + 2 * (lane & 3);
        *(float2*)(y0 + col) = make_float2(o[nj][0] * inv0, o[nj][1] * inv0);
        *(float2*)(y1 + col) = make_float2(o[nj][2] * inv1, o[nj][3] * inv1);
    }
}

// ---------------------------------------------------------------------------
// Launch
// ---------------------------------------------------------------------------
extern "C" void kernel_launch(void* const* d_in, const int* in_sizes, int n_in,
                              void* d_out, int out_size) {
    const float* x      = (const float*)d_in[0];
    const float* norm_w = (const float*)d_in[1];
    const float* qkv_w  = (const float*)d_in[2];
    const float* qkv_b  = (const float*)d_in[3];
    const float* proj_w = (const float*)d_in[4];
    const float* proj_b = (const float*)d_in[5];
    float* out = (float*)d_out;

    float *p_xn, *p_qkv, *p_y;
    __half *p_hA, *p_lA, *p_hW;
    cudaGetSymbolAddress((void**)&p_xn, g_xn);
    cudaGetSymbolAddress((void**)&p_qkv, g_qkv);
    cudaGetSymbolAddress((void**)&p_y, g_y);
    cudaGetSymbolAddress((void**)&p_hA, g_hA);
    cudaGetSymbolAddress((void**)&p_lA, g_lA);
    cudaGetSymbolAddress((void**)&p_hW, g_hW);

    cudaFuncSetAttribute(gemm_f16x2, cudaFuncAttributeMaxDynamicSharedMemorySize, GSMEM);

    // 1) RMSNorm
    rmsnorm_kernel<<<Mrows, 256>>>(x, norm_w);
    // 2) RoPE table
    rope_table_kernel<<<Ss, 32>>>();
    // 3) split xn (hi+lo) and qkv_w (hi only)
    split_f16_kernel<<<(Mrows * Dd / 4 + 255) / 256, 256>>>(
        (const float4*)p_xn, (uint2*)p_hA, (uint2*)p_lA, Mrows * Dd / 4);
    split_f16_hi_kernel<<<(QKVD * Dd / 4 + 255) / 256, 256>>>(
        (const float4*)qkv_w, (uint2*)p_hW, QKVD * Dd / 4);
    // 4) QKV GEMM (fp16 2-pass)
    gemm_f16x2<<<dim3(QKVD / 128, Mrows / 128), 256, GSMEM>>>(
        p_hA, p_lA, p_hW, qkv_b, p_qkv, Mrows, QKVD, Dd);
    // 5) fused RoPE + fp16 convert + head-major transpose
    {
        const int total = Bb * Ss * Hh * 32;
        rope_cvt_kernel<<<(total + 255) / 256, 256>>>();
    }
    // 6) tensor-core flash attention
    flash_mma_kernel<<<dim3(Ss / 64, Bb * Hh), 128>>>();
    // 7) split y (hi+lo) and proj_w (hi only)
    split_f16_kernel<<<(Mrows * Dd / 4 + 255) / 256, 256>>>(
        (const float4*)p_y, (uint2*)p_hA, (uint2*)p_lA, Mrows * Dd / 4);
    split_f16_hi_kernel<<<(Dd * Dd / 4 + 255) / 256, 256>>>(
        (const float4*)proj_w, (uint2*)p_hW, Dd * Dd / 4);
    // 8) Output projection (fp16 2-pass)
    gemm_f16x2<<<dim3(Dd / 128, Mrows / 128), 256, GSMEM>>>(
        p_hA, p_lA, p_hW, proj_b, out, Mrows, Dd, Dd);

    (void)in_sizes; (void)n_in; (void)out_size;
}

// round 8
// speedup vs baseline: 5.7110x; 1.0374x over previous
#include <cuda_runtime.h>
#include <cuda_fp16.h>
#include <cstdint>
#include <math.h>

#define Bb 2
#define Ss 2048
#define Dd 1024
#define Hh 16
#define HDIM 64
#define Mrows (Bb*Ss)   // 4096
#define QKVD (3*Dd)     // 3072

// ---------------------------------------------------------------------------
// Scratch
// ---------------------------------------------------------------------------
__device__ float g_qkv[(size_t)Mrows * QKVD];
__device__ float g_cos[Ss * 32];
__device__ float g_sin[Ss * 32];
__device__ __half g_hA[(size_t)Mrows * Dd];
__device__ __half g_lA[(size_t)Mrows * Dd];
__device__ __half g_hW[(size_t)QKVD * Dd];
// head-major fp16 q/k/v for attention: [b*16+h][s][64]
__device__ __half g_qh[(size_t)Bb * Hh * Ss * HDIM];
__device__ __half g_kh[(size_t)Bb * Hh * Ss * HDIM];
__device__ __half g_vh[(size_t)Bb * Hh * Ss * HDIM];

// ---------------------------------------------------------------------------
// Helpers
// ---------------------------------------------------------------------------
__device__ __forceinline__ uint32_t smem_to_u32(const void* p) {
    uint32_t a;
    asm("{ .reg .u64 t; cvta.to.shared.u64 t, %1; cvt.u32.u64 %0, t; }"
        : "=r"(a) : "l"(p));
    return a;
}
__device__ __forceinline__ void ldsm_x4(uint32_t addr, uint32_t& r0, uint32_t& r1,
                                        uint32_t& r2, uint32_t& r3) {
    asm volatile("ldmatrix.sync.aligned.m8n8.x4.shared.b16 {%0,%1,%2,%3}, [%4];"
                 : "=r"(r0), "=r"(r1), "=r"(r2), "=r"(r3) : "r"(addr));
}
__device__ __forceinline__ void ldsm_x4t(uint32_t addr, uint32_t& r0, uint32_t& r1,
                                         uint32_t& r2, uint32_t& r3) {
    asm volatile("ldmatrix.sync.aligned.m8n8.x4.trans.shared.b16 {%0,%1,%2,%3}, [%4];"
                 : "=r"(r0), "=r"(r1), "=r"(r2), "=r"(r3) : "r"(addr));
}
__device__ __forceinline__ void mma16816(float* c, const uint32_t* a, const uint32_t* b) {
    asm volatile("mma.sync.aligned.m16n8k16.row.col.f32.f16.f16.f32 "
                 "{%0,%1,%2,%3}, {%4,%5,%6,%7}, {%8,%9}, {%0,%1,%2,%3};"
                 : "+f"(c[0]), "+f"(c[1]), "+f"(c[2]), "+f"(c[3])
                 : "r"(a[0]), "r"(a[1]), "r"(a[2]), "r"(a[3]), "r"(b[0]), "r"(b[1]));
}
#define CP_ASYNC16(sa, ga) \
    asm volatile("cp.async.cg.shared.global [%0], [%1], 16;" :: "r"(sa), "l"(ga))
#define CP_COMMIT() asm volatile("cp.async.commit_group;" ::: "memory")
#define CP_WAIT1()  asm volatile("cp.async.wait_group 1;" ::: "memory")
#define CP_WAIT0()  asm volatile("cp.async.wait_group 0;" ::: "memory")

__device__ __forceinline__ uint32_t packf2h(float a, float b) {
    __half2 h = __floats2half2_rn(a, b);
    return *(uint32_t*)&h;
}
__device__ __forceinline__ uint32_t packh(__half a, __half b) {
    return ((uint32_t)__half_as_ushort(b) << 16) | (uint32_t)__half_as_ushort(a);
}

// ---------------------------------------------------------------------------
// Fused RMSNorm + fp16 hi/lo split: x -> (g_hA, g_lA)
// One block per row; each thread owns 4 consecutive elements.
// ---------------------------------------------------------------------------
__global__ void __launch_bounds__(256)
rmsnorm_split_kernel(const float* __restrict__ x, const float* __restrict__ w) {
    const int row = blockIdx.x;
    const float4* xr = (const float4*)(x + (size_t)row * Dd);
    const float4 v = xr[threadIdx.x];
    float ss = v.x * v.x + v.y * v.y + v.z * v.z + v.w * v.w;
    __shared__ float red[8];
    #pragma unroll
    for (int o = 16; o > 0; o >>= 1) ss += __shfl_xor_sync(0xffffffffu, ss, o);
    const int wid = threadIdx.x >> 5, lid = threadIdx.x & 31;
    if (lid == 0) red[wid] = ss;
    __syncthreads();
    if (wid == 0) {
        ss = (lid < 8) ? red[lid] : 0.f;
        #pragma unroll
        for (int o = 4; o > 0; o >>= 1) ss += __shfl_xor_sync(0xffffffffu, ss, o);
        if (lid == 0) red[0] = ss;
    }
    __syncthreads();
    const float inv = rsqrtf(red[0] * (1.0f / Dd) + 1e-6f);
    const float4 wv = ((const float4*)w)[threadIdx.x];
    const float f0 = v.x * inv * wv.x, f1 = v.y * inv * wv.y;
    const float f2 = v.z * inv * wv.z, f3 = v.w * inv * wv.w;
    const __half h0 = __float2half_rn(f0), h1 = __float2half_rn(f1);
    const __half h2 = __float2half_rn(f2), h3 = __float2half_rn(f3);
    const __half l0 = __float2half_rn(f0 - __half2float(h0));
    const __half l1 = __float2half_rn(f1 - __half2float(h1));
    const __half l2 = __float2half_rn(f2 - __half2float(h2));
    const __half l3 = __float2half_rn(f3 - __half2float(h3));
    const size_t o4 = (size_t)row * (Dd / 4) + threadIdx.x;
    ((uint2*)g_hA)[o4] = make_uint2(packh(h0, h1), packh(h2, h3));
    ((uint2*)g_lA)[o4] = make_uint2(packh(l0, l1), packh(l2, l3));
}

// ---------------------------------------------------------------------------
// RoPE table
// ---------------------------------------------------------------------------
__global__ void rope_table_kernel() {
    const int t = blockIdx.x;
    const int i = threadIdx.x;
    double inv = pow(10000.0, -((double)(2 * i)) / 64.0);
    double a = (double)t * inv;
    g_cos[t * 32 + i] = (float)cos(a);
    g_sin[t * 32 + i] = (float)sin(a);
}

// ---------------------------------------------------------------------------
// Fused RoPE + fp16 convert + head-major transpose for q,k,v
// q pre-scaled by 0.125
// ---------------------------------------------------------------------------
__global__ void rope_cvt_kernel() {
    const int idx = blockIdx.x * blockDim.x + threadIdx.x;
    if (idx >= Bb * Ss * Hh * 32) return;
    const int j = idx & 31;
    const int h = (idx >> 5) & (Hh - 1);
    const int s = (idx >> 9) & (Ss - 1);
    const int b = idx >> 20;
    const float c = g_cos[s * 32 + j];
    const float sn = g_sin[s * 32 + j];
    const size_t base = ((size_t)(b * Ss + s)) * QKVD + h * HDIM + j;
    const size_t ob = ((size_t)(b * Hh + h) * Ss + s) * HDIM + j;
    float q1 = g_qkv[base], q2 = g_qkv[base + 32];
    g_qh[ob]      = __float2half_rn((q1 * c - q2 * sn) * 0.125f);
    g_qh[ob + 32] = __float2half_rn((q2 * c + q1 * sn) * 0.125f);
    float k1 = g_qkv[base + Dd], k2 = g_qkv[base + Dd + 32];
    g_kh[ob]      = __float2half_rn(k1 * c - k2 * sn);
    g_kh[ob + 32] = __float2half_rn(k2 * c + k1 * sn);
    g_vh[ob]      = __float2half_rn(g_qkv[base + 2 * Dd]);
    g_vh[ob + 32] = __float2half_rn(g_qkv[base + 2 * Dd + 32]);
}

// ---------------------------------------------------------------------------
// fp32 -> fp16 hi-only (weights)
// ---------------------------------------------------------------------------
__global__ void split_f16_hi_kernel(const float4* __restrict__ src,
                                    uint2* __restrict__ hi, int n4) {
    int i = blockIdx.x * blockDim.x + threadIdx.x;
    if (i >= n4) return;
    float4 v = src[i];
    hi[i] = make_uint2(packh(__float2half_rn(v.x), __float2half_rn(v.y)),
                       packh(__float2half_rn(v.z), __float2half_rn(v.w)));
}

// ---------------------------------------------------------------------------
// Split-precision GEMM via mma.sync fp16, 2 passes
// ---------------------------------------------------------------------------
#define PADB  80
#define TILEB (128 * PADB)
#define STAGEB (3 * TILEB)
#define NSTAGE 3
#define GSMEM (NSTAGE * STAGEB)

__global__ void __launch_bounds__(256)
gemm_f16x2(const __half* __restrict__ Ahi, const __half* __restrict__ Alo,
           const __half* __restrict__ Whi,
           const float* __restrict__ bias, float* __restrict__ C,
           int M, int N, int K) {
    extern __shared__ char smem[];
    const uint32_t sb = smem_to_u32(smem);
    const int tid = threadIdx.x, lane = tid & 31, w = tid >> 5;
    const int bm = blockIdx.y * 128, bn = blockIdx.x * 128;
    const int wm = (w >> 1) * 32, wn = (w & 1) * 64;

    const __half* srcs[3] = {Ahi, Alo, Whi};
    const int rb[3] = {bm, bm, bn};

    auto load_stage = [&](int s, int k0) {
        const uint32_t st = sb + s * STAGEB;
        #pragma unroll
        for (int t = 0; t < 3; t++) {
            const __half* src = srcs[t] + (size_t)rb[t] * K + k0;
            const uint32_t tb = st + t * TILEB;
            #pragma unroll
            for (int j = 0; j < 2; j++) {
                const int c = tid + j * 256;
                const int row = c >> 2, c16 = c & 3;
                const uint32_t sa = tb + row * PADB + c16 * 16;
                const __half* ga = src + (size_t)row * K + c16 * 8;
                CP_ASYNC16(sa, ga);
            }
        }
    };

    float acc[2][8][4];
    #pragma unroll
    for (int mi = 0; mi < 2; mi++)
        #pragma unroll
        for (int nj = 0; nj < 8; nj++)
            #pragma unroll
            for (int r = 0; r < 4; r++) acc[mi][nj][r] = 0.f;

    load_stage(0, 0);  CP_COMMIT();
    load_stage(1, 32); CP_COMMIT();

    const int nch = K >> 5;
    const int sel = lane >> 3;
    const int asub = (sel & 1) * 8, ak8 = (sel >> 1) * 8;
    const int nsub = (sel >> 1) * 8, bk8 = (sel & 1) * 8;

    for (int cidx = 0; cidx < nch; cidx++) {
        CP_WAIT1();
        __syncthreads();
        if (cidx + 2 < nch) load_stage((cidx + 2) % NSTAGE, (cidx + 2) * 32);
        CP_COMMIT();

        const uint32_t st = sb + (cidx % NSTAGE) * STAGEB;
        #pragma unroll
        for (int kk = 0; kk < 2; kk++) {
            const int ko = kk * 16;
            uint32_t ah[2][4], al[2][4], wh[8][2];
            #pragma unroll
            for (int mi = 0; mi < 2; mi++) {
                const uint32_t addr = st + (wm + mi * 16 + (lane & 7) + asub) * PADB
                                      + (ko + ak8) * 2;
                ldsm_x4(addr, ah[mi][0], ah[mi][1], ah[mi][2], ah[mi][3]);
                ldsm_x4(addr + TILEB, al[mi][0], al[mi][1], al[mi][2], al[mi][3]);
            }
            #pragma unroll
            for (int ni = 0; ni < 4; ni++) {
                const uint32_t addr = st + 2 * TILEB
                                      + (wn + ni * 16 + (lane & 7) + nsub) * PADB
                                      + (ko + bk8) * 2;
                uint32_t r0, r1, r2, r3;
                ldsm_x4(addr, r0, r1, r2, r3);
                wh[ni * 2][0] = r0; wh[ni * 2][1] = r1;
                wh[ni * 2 + 1][0] = r2; wh[ni * 2 + 1][1] = r3;
            }
            #pragma unroll
            for (int mi = 0; mi < 2; mi++)
                #pragma unroll
                for (int nj = 0; nj < 8; nj++)
                    mma16816(acc[mi][nj], ah[mi], wh[nj]);
            #pragma unroll
            for (int mi = 0; mi < 2; mi++)
                #pragma unroll
                for (int nj = 0; nj < 8; nj++)
                    mma16816(acc[mi][nj], al[mi], wh[nj]);
        }
    }

    #pragma unroll
    for (int mi = 0; mi < 2; mi++) {
        const int row = bm + wm + mi * 16 + (lane >> 2);
        #pragma unroll
        for (int nj = 0; nj < 8; nj++) {
            const int col = bn + wn + nj * 8 + (lane & 3) * 2;
            const float b0 = bias[col], b1 = bias[col + 1];
            float2* c0 = (float2*)(C + (size_t)row * N + col);
            float2* c1 = (float2*)(C + (size_t)(row + 8) * N + col);
            *c0 = make_float2(acc[mi][nj][0] + b0, acc[mi][nj][1] + b1);
            *c1 = make_float2(acc[mi][nj][2] + b0, acc[mi][nj][3] + b1);
        }
    }
}

// ---------------------------------------------------------------------------
// Tensor-core flash attention (causal). Epilogue writes hi/lo fp16 for the
// projection GEMM directly (no fp32 y round trip).
// ---------------------------------------------------------------------------
#define FROWH 72
#define FROWB (FROWH * 2)
#define FTILE (64 * FROWB)

__global__ void __launch_bounds__(128)
flash_mma_kernel() {
    __shared__ __align__(16) char fsm[5 * FTILE];   // Q | K0 | K1 | V0 | V1
    const int qblk = gridDim.x - 1 - blockIdx.x;    // long CTAs first
    const int bh = blockIdx.y;
    const int tid = threadIdx.x, lane = tid & 31, w = tid >> 5;
    const int qbase = qblk * 64, wm = w * 16;
    const uint32_t sq = smem_to_u32(fsm);
    const uint32_t sk0 = sq + FTILE, sk1 = sq + 2 * FTILE;
    const uint32_t sv0 = sq + 3 * FTILE, sv1 = sq + 4 * FTILE;

    const size_t hb = (size_t)bh * Ss * HDIM;

    {
        const __half* qsrc = g_qh + hb + (size_t)qbase * HDIM;
        #pragma unroll
        for (int i = 0; i < 4; i++) {
            const int c = tid + i * 128;
            const int row = c >> 3, col = (c & 7) * 8;
            CP_ASYNC16(sq + row * FROWB + col * 2, qsrc + row * HDIM + col);
        }
    }
    auto fetch_kv = [&](int kt) {
        const __half* ksrc = g_kh + hb + (size_t)(kt * 64) * HDIM;
        const __half* vsrc = g_vh + hb + (size_t)(kt * 64) * HDIM;
        const uint32_t kb = (kt & 1) ? sk1 : sk0;
        const uint32_t vb = (kt & 1) ? sv1 : sv0;
        #pragma unroll
        for (int i = 0; i < 4; i++) {
            const int c = tid + i * 128;
            const int row = c >> 3, col = (c & 7) * 8;
            CP_ASYNC16(kb + row * FROWB + col * 2, ksrc + row * HDIM + col);
            CP_ASYNC16(vb + row * FROWB + col * 2, vsrc + row * HDIM + col);
        }
    };
    const int nt = qblk + 1;
    fetch_kv(0); CP_COMMIT();
    if (nt > 1) { fetch_kv(1); CP_COMMIT(); }

    uint32_t qf[4][4];
    float o[8][4];
    #pragma unroll
    for (int nj = 0; nj < 8; nj++)
        #pragma unroll
        for (int r = 0; r < 4; r++) o[nj][r] = 0.f;
    float mrow0 = -INFINITY, mrow1 = -INFINITY, lrow0 = 0.f, lrow1 = 0.f;

    for (int kt = 0; kt < nt; kt++) {
        if (kt + 1 < nt) {
            if (kt) { fetch_kv(kt + 1); CP_COMMIT(); }
            CP_WAIT1();
        } else {
            CP_WAIT0();
        }
        __syncthreads();

        if (kt == 0) {
            #pragma unroll
            for (int ks = 0; ks < 4; ks++) {
                const uint32_t addr = sq + (wm + (lane & 15)) * FROWB
                                      + (ks * 16 + (lane >> 4) * 8) * 2;
                ldsm_x4(addr, qf[ks][0], qf[ks][1], qf[ks][2], qf[ks][3]);
            }
        }

        const uint32_t kb = (kt & 1) ? sk1 : sk0;
        const uint32_t vb = (kt & 1) ? sv1 : sv0;

        float s[8][4];
        #pragma unroll
        for (int nj = 0; nj < 8; nj++)
            #pragma unroll
            for (int r = 0; r < 4; r++) s[nj][r] = 0.f;
        const int sel = lane >> 3;
        #pragma unroll
        for (int ks = 0; ks < 4; ks++) {
            #pragma unroll
            for (int np = 0; np < 4; np++) {
                const uint32_t addr = kb
                    + (np * 16 + (lane & 7) + (sel >> 1) * 8) * FROWB
                    + (ks * 16 + (sel & 1) * 8) * 2;
                uint32_t r0, r1, r2, r3;
                ldsm_x4(addr, r0, r1, r2, r3);
                uint32_t b0[2] = {r0, r1}, b1[2] = {r2, r3};
                mma16816(s[np * 2], qf[ks], b0);
                mma16816(s[np * 2 + 1], qf[ks], b1);
            }
        }

        if (kt == qblk) {
            const int lr0 = wm + (lane >> 2), lr1 = lr0 + 8;
            #pragma unroll
            for (int nj = 0; nj < 8; nj++) {
                const int ck = nj * 8 + 2 * (lane & 3);
                if (ck > lr0)     s[nj][0] = -INFINITY;
                if (ck + 1 > lr0) s[nj][1] = -INFINITY;
                if (ck > lr1)     s[nj][2] = -INFINITY;
                if (ck + 1 > lr1) s[nj][3] = -INFINITY;
            }
        }

        float mx0 = -INFINITY, mx1 = -INFINITY;
        #pragma unroll
        for (int nj = 0; nj < 8; nj++) {
            mx0 = fmaxf(mx0, fmaxf(s[nj][0], s[nj][1]));
            mx1 = fmaxf(mx1, fmaxf(s[nj][2], s[nj][3]));
        }
        mx0 = fmaxf(mx0, __shfl_xor_sync(0xffffffffu, mx0, 1));
        mx0 = fmaxf(mx0, __shfl_xor_sync(0xffffffffu, mx0, 2));
        mx1 = fmaxf(mx1, __shfl_xor_sync(0xffffffffu, mx1, 1));
        mx1 = fmaxf(mx1, __shfl_xor_sync(0xffffffffu, mx1, 2));
        const float mn0 = fmaxf(mrow0, mx0), mn1 = fmaxf(mrow1, mx1);
        const float c0 = __expf(mrow0 - mn0), c1 = __expf(mrow1 - mn1);
        float sum0 = 0.f, sum1 = 0.f;
        #pragma unroll
        for (int nj = 0; nj < 8; nj++) {
            s[nj][0] = __expf(s[nj][0] - mn0);
            s[nj][1] = __expf(s[nj][1] - mn0);
            s[nj][2] = __expf(s[nj][2] - mn1);
            s[nj][3] = __expf(s[nj][3] - mn1);
            sum0 += s[nj][0] + s[nj][1];
            sum1 += s[nj][2] + s[nj][3];
        }
        sum0 += __shfl_xor_sync(0xffffffffu, sum0, 1);
        sum0 += __shfl_xor_sync(0xffffffffu, sum0, 2);
        sum1 += __shfl_xor_sync(0xffffffffu, sum1, 1);
        sum1 += __shfl_xor_sync(0xffffffffu, sum1, 2);
        lrow0 = lrow0 * c0 + sum0;
        lrow1 = lrow1 * c1 + sum1;
        #pragma unroll
        for (int nj = 0; nj < 8; nj++) {
            o[nj][0] *= c0; o[nj][1] *= c0;
            o[nj][2] *= c1; o[nj][3] *= c1;
        }
        mrow0 = mn0; mrow1 = mn1;

        #pragma unroll
        for (int ks = 0; ks < 4; ks++) {
            uint32_t a[4];
            a[0] = packf2h(s[2 * ks][0], s[2 * ks][1]);
            a[1] = packf2h(s[2 * ks][2], s[2 * ks][3]);
            a[2] = packf2h(s[2 * ks + 1][0], s[2 * ks + 1][1]);
            a[3] = packf2h(s[2 * ks + 1][2], s[2 * ks + 1][3]);
            #pragma unroll
            for (int np = 0; np < 4; np++) {
                const uint32_t addr = vb
                    + (ks * 16 + (lane & 7) + (lane & 8)) * FROWB
                    + (np * 16 + ((lane >> 4) & 1) * 8) * 2;
                uint32_t r0, r1, r2, r3;
                ldsm_x4t(addr, r0, r1, r2, r3);
                uint32_t b0[2] = {r0, r1}, b1[2] = {r2, r3};
                mma16816(o[np * 2], a, b0);
                mma16816(o[np * 2 + 1], a, b1);
            }
        }
        __syncthreads();
    }

    // epilogue: write hi/lo fp16 directly (input to projection GEMM)
    const float inv0 = 1.f / lrow0, inv1 = 1.f / lrow1;
    const int b = bh >> 4, h = bh & 15;
    const int row0 = qbase + wm + (lane >> 2);
    const size_t y0 = ((size_t)(b * Ss + row0)) * Dd + h * HDIM;
    const size_t y1 = y0 + (size_t)8 * Dd;
    #pragma unroll
    for (int nj = 0; nj < 8; nj++) {
        const int col = nj * 8 + 2 * (lane & 3);
        const float v00 = o[nj][0] * inv0, v01 = o[nj][1] * inv0;
        const float v10 = o[nj][2] * inv1, v11 = o[nj][3] * inv1;
        const __half h00 = __float2half_rn(v00), h01 = __float2half_rn(v01);
        const __half h10 = __float2half_rn(v10), h11 = __float2half_rn(v11);
        *(uint32_t*)(g_hA + y0 + col) = packh(h00, h01);
        *(uint32_t*)(g_hA + y1 + col) = packh(h10, h11);
        *(uint32_t*)(g_lA + y0 + col) =
            packh(__float2half_rn(v00 - __half2float(h00)),
                  __float2half_rn(v01 - __half2float(h01)));
        *(uint32_t*)(g_lA + y1 + col) =
            packh(__float2half_rn(v10 - __half2float(h10)),
                  __float2half_rn(v11 - __half2float(h11)));
    }
}

// ---------------------------------------------------------------------------
// Launch
// ---------------------------------------------------------------------------
extern "C" void kernel_launch(void* const* d_in, const int* in_sizes, int n_in,
                              void* d_out, int out_size) {
    const float* x      = (const float*)d_in[0];
    const float* norm_w = (const float*)d_in[1];
    const float* qkv_w  = (const float*)d_in[2];
    const float* qkv_b  = (const float*)d_in[3];
    const float* proj_w = (const float*)d_in[4];
    const float* proj_b = (const float*)d_in[5];
    float* out = (float*)d_out;

    float* p_qkv;
    __half *p_hA, *p_lA, *p_hW;
    cudaGetSymbolAddress((void**)&p_qkv, g_qkv);
    cudaGetSymbolAddress((void**)&p_hA, g_hA);
    cudaGetSymbolAddress((void**)&p_lA, g_lA);
    cudaGetSymbolAddress((void**)&p_hW, g_hW);

    cudaFuncSetAttribute(gemm_f16x2, cudaFuncAttributeMaxDynamicSharedMemorySize, GSMEM);

    // 1) fused RMSNorm + hi/lo split -> g_hA/g_lA
    rmsnorm_split_kernel<<<Mrows, 256>>>(x, norm_w);
    // 2) RoPE table
    rope_table_kernel<<<Ss, 32>>>();
    // 3) weights hi split
    split_f16_hi_kernel<<<(QKVD * Dd / 4 + 255) / 256, 256>>>(
        (const float4*)qkv_w, (uint2*)p_hW, QKVD * Dd / 4);
    // 4) QKV GEMM (fp16 2-pass)
    gemm_f16x2<<<dim3(QKVD / 128, Mrows / 128), 256, GSMEM>>>(
        p_hA, p_lA, p_hW, qkv_b, p_qkv, Mrows, QKVD, Dd);
    // 5) fused RoPE + fp16 convert + head-major transpose
    {
        const int total = Bb * Ss * Hh * 32;
        rope_cvt_kernel<<<(total + 255) / 256, 256>>>();
    }
    // 6) tensor-core flash attention (writes hi/lo y directly)
    flash_mma_kernel<<<dim3(Ss / 64, Bb * Hh), 128>>>();
    // 7) proj weights hi split
    split_f16_hi_kernel<<<(Dd * Dd / 4 + 255) / 256, 256>>>(
        (const float4*)proj_w, (uint2*)p_hW, Dd * Dd / 4);
    // 8) Output projection (fp16 2-pass)
    gemm_f16x2<<<dim3(Dd / 128, Mrows / 128), 256, GSMEM>>>(
        p_hA, p_lA, p_hW, proj_b, out, Mrows, Dd, Dd);

    (void)in_sizes; (void)n_in; (void)out_size;
}

// round 9
// speedup vs baseline: 7.1648x; 1.2546x over previous
#include <cuda_runtime.h>
#include <cuda_fp16.h>
#include <cstdint>
#include <math.h>

#define Bb 2
#define Ss 2048
#define Dd 1024
#define Hh 16
#define HDIM 64
#define Mrows (Bb*Ss)   // 4096
#define QKVD (3*Dd)     // 3072

// ---------------------------------------------------------------------------
// Scratch
// ---------------------------------------------------------------------------
__device__ float g_qkv[(size_t)Mrows * QKVD];
__device__ float g_cos[Ss * 32];
__device__ float g_sin[Ss * 32];
__device__ __half g_hA[(size_t)Mrows * Dd];
__device__ __half g_hW[(size_t)QKVD * Dd];
// head-major fp16 q/k/v for attention: [b*16+h][s][64]
__device__ __half g_qh[(size_t)Bb * Hh * Ss * HDIM];
__device__ __half g_kh[(size_t)Bb * Hh * Ss * HDIM];
__device__ __half g_vh[(size_t)Bb * Hh * Ss * HDIM];

// ---------------------------------------------------------------------------
// Helpers
// ---------------------------------------------------------------------------
__device__ __forceinline__ uint32_t smem_to_u32(const void* p) {
    uint32_t a;
    asm("{ .reg .u64 t; cvta.to.shared.u64 t, %1; cvt.u32.u64 %0, t; }"
        : "=r"(a) : "l"(p));
    return a;
}
__device__ __forceinline__ void ldsm_x4(uint32_t addr, uint32_t& r0, uint32_t& r1,
                                        uint32_t& r2, uint32_t& r3) {
    asm volatile("ldmatrix.sync.aligned.m8n8.x4.shared.b16 {%0,%1,%2,%3}, [%4];"
                 : "=r"(r0), "=r"(r1), "=r"(r2), "=r"(r3) : "r"(addr));
}
__device__ __forceinline__ void ldsm_x4t(uint32_t addr, uint32_t& r0, uint32_t& r1,
                                         uint32_t& r2, uint32_t& r3) {
    asm volatile("ldmatrix.sync.aligned.m8n8.x4.trans.shared.b16 {%0,%1,%2,%3}, [%4];"
                 : "=r"(r0), "=r"(r1), "=r"(r2), "=r"(r3) : "r"(addr));
}
__device__ __forceinline__ void mma16816(float* c, const uint32_t* a, const uint32_t* b) {
    asm volatile("mma.sync.aligned.m16n8k16.row.col.f32.f16.f16.f32 "
                 "{%0,%1,%2,%3}, {%4,%5,%6,%7}, {%8,%9}, {%0,%1,%2,%3};"
                 : "+f"(c[0]), "+f"(c[1]), "+f"(c[2]), "+f"(c[3])
                 : "r"(a[0]), "r"(a[1]), "r"(a[2]), "r"(a[3]), "r"(b[0]), "r"(b[1]));
}
#define CP_ASYNC16(sa, ga) \
    asm volatile("cp.async.cg.shared.global [%0], [%1], 16;" :: "r"(sa), "l"(ga))
#define CP_COMMIT() asm volatile("cp.async.commit_group;" ::: "memory")
#define CP_WAIT1()  asm volatile("cp.async.wait_group 1;" ::: "memory")
#define CP_WAIT0()  asm volatile("cp.async.wait_group 0;" ::: "memory")

__device__ __forceinline__ uint32_t packf2h(float a, float b) {
    __half2 h = __floats2half2_rn(a, b);
    return *(uint32_t*)&h;
}
__device__ __forceinline__ uint32_t packh(__half a, __half b) {
    return ((uint32_t)__half_as_ushort(b) << 16) | (uint32_t)__half_as_ushort(a);
}

// ---------------------------------------------------------------------------
// Fused RMSNorm + fp16 convert: x -> g_hA
// ---------------------------------------------------------------------------
__global__ void __launch_bounds__(256)
rmsnorm_h_kernel(const float* __restrict__ x, const float* __restrict__ w) {
    const int row = blockIdx.x;
    const float4* xr = (const float4*)(x + (size_t)row * Dd);
    const float4 v = xr[threadIdx.x];
    float ss = v.x * v.x + v.y * v.y + v.z * v.z + v.w * v.w;
    __shared__ float red[8];
    #pragma unroll
    for (int o = 16; o > 0; o >>= 1) ss += __shfl_xor_sync(0xffffffffu, ss, o);
    const int wid = threadIdx.x >> 5, lid = threadIdx.x & 31;
    if (lid == 0) red[wid] = ss;
    __syncthreads();
    if (wid == 0) {
        ss = (lid < 8) ? red[lid] : 0.f;
        #pragma unroll
        for (int o = 4; o > 0; o >>= 1) ss += __shfl_xor_sync(0xffffffffu, ss, o);
        if (lid == 0) red[0] = ss;
    }
    __syncthreads();
    const float inv = rsqrtf(red[0] * (1.0f / Dd) + 1e-6f);
    const float4 wv = ((const float4*)w)[threadIdx.x];
    const size_t o4 = (size_t)row * (Dd / 4) + threadIdx.x;
    ((uint2*)g_hA)[o4] = make_uint2(
        packh(__float2half_rn(v.x * inv * wv.x), __float2half_rn(v.y * inv * wv.y)),
        packh(__float2half_rn(v.z * inv * wv.z), __float2half_rn(v.w * inv * wv.w)));
}

// ---------------------------------------------------------------------------
// RoPE table
// ---------------------------------------------------------------------------
__global__ void rope_table_kernel() {
    const int t = blockIdx.x;
    const int i = threadIdx.x;
    double inv = pow(10000.0, -((double)(2 * i)) / 64.0);
    double a = (double)t * inv;
    g_cos[t * 32 + i] = (float)cos(a);
    g_sin[t * 32 + i] = (float)sin(a);
}

// ---------------------------------------------------------------------------
// Fused RoPE + fp16 convert + head-major transpose for q,k,v (q pre-scaled)
// ---------------------------------------------------------------------------
__global__ void rope_cvt_kernel() {
    const int idx = blockIdx.x * blockDim.x + threadIdx.x;
    if (idx >= Bb * Ss * Hh * 32) return;
    const int j = idx & 31;
    const int h = (idx >> 5) & (Hh - 1);
    const int s = (idx >> 9) & (Ss - 1);
    const int b = idx >> 20;
    const float c = g_cos[s * 32 + j];
    const float sn = g_sin[s * 32 + j];
    const size_t base = ((size_t)(b * Ss + s)) * QKVD + h * HDIM + j;
    const size_t ob = ((size_t)(b * Hh + h) * Ss + s) * HDIM + j;
    float q1 = g_qkv[base], q2 = g_qkv[base + 32];
    g_qh[ob]      = __float2half_rn((q1 * c - q2 * sn) * 0.125f);
    g_qh[ob + 32] = __float2half_rn((q2 * c + q1 * sn) * 0.125f);
    float k1 = g_qkv[base + Dd], k2 = g_qkv[base + Dd + 32];
    g_kh[ob]      = __float2half_rn(k1 * c - k2 * sn);
    g_kh[ob + 32] = __float2half_rn(k2 * c + k1 * sn);
    g_vh[ob]      = __float2half_rn(g_qkv[base + 2 * Dd]);
    g_vh[ob + 32] = __float2half_rn(g_qkv[base + 2 * Dd + 32]);
}

// ---------------------------------------------------------------------------
// fp32 -> fp16 (weights)
// ---------------------------------------------------------------------------
__global__ void split_f16_hi_kernel(const float4* __restrict__ src,
                                    uint2* __restrict__ hi, int n4) {
    int i = blockIdx.x * blockDim.x + threadIdx.x;
    if (i >= n4) return;
    float4 v = src[i];
    hi[i] = make_uint2(packh(__float2half_rn(v.x), __float2half_rn(v.y)),
                       packh(__float2half_rn(v.z), __float2half_rn(v.w)));
}

// ---------------------------------------------------------------------------
// Single-pass fp16 GEMM via mma.sync: C = A * W^T + bias
//   CTA 128x128, 8 warps (warp 32x64), KC=32, 3-stage cp.async, 2 tiles/stage
// ---------------------------------------------------------------------------
#define PADB  80
#define TILEB (128 * PADB)           // 10240
#define STAGEB (2 * TILEB)           // 20480: A, W
#define NSTAGE 3
#define GSMEM (NSTAGE * STAGEB)      // 61440

__global__ void __launch_bounds__(256)
gemm_f16(const __half* __restrict__ Ahi, const __half* __restrict__ Whi,
         const float* __restrict__ bias, float* __restrict__ C,
         int M, int N, int K) {
    extern __shared__ char smem[];
    const uint32_t sb = smem_to_u32(smem);
    const int tid = threadIdx.x, lane = tid & 31, w = tid >> 5;
    const int bm = blockIdx.y * 128, bn = blockIdx.x * 128;
    const int wm = (w >> 1) * 32, wn = (w & 1) * 64;

    auto load_stage = [&](int s, int k0) {
        const uint32_t st = sb + s * STAGEB;
        #pragma unroll
        for (int t = 0; t < 2; t++) {
            const __half* src = (t == 0 ? Ahi : Whi)
                                + (size_t)(t == 0 ? bm : bn) * K + k0;
            const uint32_t tb = st + t * TILEB;
            #pragma unroll
            for (int j = 0; j < 2; j++) {
                const int c = tid + j * 256;
                const int row = c >> 2, c16 = c & 3;
                const uint32_t sa = tb + row * PADB + c16 * 16;
                const __half* ga = src + (size_t)row * K + c16 * 8;
                CP_ASYNC16(sa, ga);
            }
        }
    };

    float acc[2][8][4];
    #pragma unroll
    for (int mi = 0; mi < 2; mi++)
        #pragma unroll
        for (int nj = 0; nj < 8; nj++)
            #pragma unroll
            for (int r = 0; r < 4; r++) acc[mi][nj][r] = 0.f;

    load_stage(0, 0);  CP_COMMIT();
    load_stage(1, 32); CP_COMMIT();

    const int nch = K >> 5;
    const int sel = lane >> 3;
    const int asub = (sel & 1) * 8, ak8 = (sel >> 1) * 8;
    const int nsub = (sel >> 1) * 8, bk8 = (sel & 1) * 8;

    for (int cidx = 0; cidx < nch; cidx++) {
        CP_WAIT1();
        __syncthreads();
        if (cidx + 2 < nch) load_stage((cidx + 2) % NSTAGE, (cidx + 2) * 32);
        CP_COMMIT();

        const uint32_t st = sb + (cidx % NSTAGE) * STAGEB;
        #pragma unroll
        for (int kk = 0; kk < 2; kk++) {
            const int ko = kk * 16;
            uint32_t ah[2][4], wh[8][2];
            #pragma unroll
            for (int mi = 0; mi < 2; mi++) {
                const uint32_t addr = st + (wm + mi * 16 + (lane & 7) + asub) * PADB
                                      + (ko + ak8) * 2;
                ldsm_x4(addr, ah[mi][0], ah[mi][1], ah[mi][2], ah[mi][3]);
            }
            #pragma unroll
            for (int ni = 0; ni < 4; ni++) {
                const uint32_t addr = st + TILEB
                                      + (wn + ni * 16 + (lane & 7) + nsub) * PADB
                                      + (ko + bk8) * 2;
                uint32_t r0, r1, r2, r3;
                ldsm_x4(addr, r0, r1, r2, r3);
                wh[ni * 2][0] = r0; wh[ni * 2][1] = r1;
                wh[ni * 2 + 1][0] = r2; wh[ni * 2 + 1][1] = r3;
            }
            #pragma unroll
            for (int mi = 0; mi < 2; mi++)
                #pragma unroll
                for (int nj = 0; nj < 8; nj++)
                    mma16816(acc[mi][nj], ah[mi], wh[nj]);
        }
    }

    #pragma unroll
    for (int mi = 0; mi < 2; mi++) {
        const int row = bm + wm + mi * 16 + (lane >> 2);
        #pragma unroll
        for (int nj = 0; nj < 8; nj++) {
            const int col = bn + wn + nj * 8 + (lane & 3) * 2;
            const float b0 = bias[col], b1 = bias[col + 1];
            float2* c0 = (float2*)(C + (size_t)row * N + col);
            float2* c1 = (float2*)(C + (size_t)(row + 8) * N + col);
            *c0 = make_float2(acc[mi][nj][0] + b0, acc[mi][nj][1] + b1);
            *c1 = make_float2(acc[mi][nj][2] + b0, acc[mi][nj][3] + b1);
        }
    }
}

// ---------------------------------------------------------------------------
// Tensor-core flash attention (causal). Epilogue writes fp16 y into g_hA.
// ---------------------------------------------------------------------------
#define FROWH 72
#define FROWB (FROWH * 2)
#define FTILE (64 * FROWB)

__global__ void __launch_bounds__(128)
flash_mma_kernel() {
    __shared__ __align__(16) char fsm[5 * FTILE];   // Q | K0 | K1 | V0 | V1
    const int qblk = gridDim.x - 1 - blockIdx.x;    // long CTAs first
    const int bh = blockIdx.y;
    const int tid = threadIdx.x, lane = tid & 31, w = tid >> 5;
    const int qbase = qblk * 64, wm = w * 16;
    const uint32_t sq = smem_to_u32(fsm);
    const uint32_t sk0 = sq + FTILE, sk1 = sq + 2 * FTILE;
    const uint32_t sv0 = sq + 3 * FTILE, sv1 = sq + 4 * FTILE;

    const size_t hb = (size_t)bh * Ss * HDIM;

    {
        const __half* qsrc = g_qh + hb + (size_t)qbase * HDIM;
        #pragma unroll
        for (int i = 0; i < 4; i++) {
            const int c = tid + i * 128;
            const int row = c >> 3, col = (c & 7) * 8;
            CP_ASYNC16(sq + row * FROWB + col * 2, qsrc + row * HDIM + col);
        }
    }
    auto fetch_kv = [&](int kt) {
        const __half* ksrc = g_kh + hb + (size_t)(kt * 64) * HDIM;
        const __half* vsrc = g_vh + hb + (size_t)(kt * 64) * HDIM;
        const uint32_t kb = (kt & 1) ? sk1 : sk0;
        const uint32_t vb = (kt & 1) ? sv1 : sv0;
        #pragma unroll
        for (int i = 0; i < 4; i++) {
            const int c = tid + i * 128;
            const int row = c >> 3, col = (c & 7) * 8;
            CP_ASYNC16(kb + row * FROWB + col * 2, ksrc + row * HDIM + col);
            CP_ASYNC16(vb + row * FROWB + col * 2, vsrc + row * HDIM + col);
        }
    };
    const int nt = qblk + 1;
    fetch_kv(0); CP_COMMIT();
    if (nt > 1) { fetch_kv(1); CP_COMMIT(); }

    uint32_t qf[4][4];
    float o[8][4];
    #pragma unroll
    for (int nj = 0; nj < 8; nj++)
        #pragma unroll
        for (int r = 0; r < 4; r++) o[nj][r] = 0.f;
    float mrow0 = -INFINITY, mrow1 = -INFINITY, lrow0 = 0.f, lrow1 = 0.f;

    for (int kt = 0; kt < nt; kt++) {
        if (kt + 1 < nt) {
            if (kt) { fetch_kv(kt + 1); CP_COMMIT(); }
            CP_WAIT1();
        } else {
            CP_WAIT0();
        }
        __syncthreads();

        if (kt == 0) {
            #pragma unroll
            for (int ks = 0; ks < 4; ks++) {
                const uint32_t addr = sq + (wm + (lane & 15)) * FROWB
                                      + (ks * 16 + (lane >> 4) * 8) * 2;
                ldsm_x4(addr, qf[ks][0], qf[ks][1], qf[ks][2], qf[ks][3]);
            }
        }

        const uint32_t kb = (kt & 1) ? sk1 : sk0;
        const uint32_t vb = (kt & 1) ? sv1 : sv0;

        float s[8][4];
        #pragma unroll
        for (int nj = 0; nj < 8; nj++)
            #pragma unroll
            for (int r = 0; r < 4; r++) s[nj][r] = 0.f;
        const int sel = lane >> 3;
        #pragma unroll
        for (int ks = 0; ks < 4; ks++) {
            #pragma unroll
            for (int np = 0; np < 4; np++) {
                const uint32_t addr = kb
                    + (np * 16 + (lane & 7) + (sel >> 1) * 8) * FROWB
                    + (ks * 16 + (sel & 1) * 8) * 2;
                uint32_t r0, r1, r2, r3;
                ldsm_x4(addr, r0, r1, r2, r3);
                uint32_t b0[2] = {r0, r1}, b1[2] = {r2, r3};
                mma16816(s[np * 2], qf[ks], b0);
                mma16816(s[np * 2 + 1], qf[ks], b1);
            }
        }

        if (kt == qblk) {
            const int lr0 = wm + (lane >> 2), lr1 = lr0 + 8;
            #pragma unroll
            for (int nj = 0; nj < 8; nj++) {
                const int ck = nj * 8 + 2 * (lane & 3);
                if (ck > lr0)     s[nj][0] = -INFINITY;
                if (ck + 1 > lr0) s[nj][1] = -INFINITY;
                if (ck > lr1)     s[nj][2] = -INFINITY;
                if (ck + 1 > lr1) s[nj][3] = -INFINITY;
            }
        }

        float mx0 = -INFINITY, mx1 = -INFINITY;
        #pragma unroll
        for (int nj = 0; nj < 8; nj++) {
            mx0 = fmaxf(mx0, fmaxf(s[nj][0], s[nj][1]));
            mx1 = fmaxf(mx1, fmaxf(s[nj][2], s[nj][3]));
        }
        mx0 = fmaxf(mx0, __shfl_xor_sync(0xffffffffu, mx0, 1));
        mx0 = fmaxf(mx0, __shfl_xor_sync(0xffffffffu, mx0, 2));
        mx1 = fmaxf(mx1, __shfl_xor_sync(0xffffffffu, mx1, 1));
        mx1 = fmaxf(mx1, __shfl_xor_sync(0xffffffffu, mx1, 2));
        const float mn0 = fmaxf(mrow0, mx0), mn1 = fmaxf(mrow1, mx1);
        const float c0 = __expf(mrow0 - mn0), c1 = __expf(mrow1 - mn1);
        float sum0 = 0.f, sum1 = 0.f;
        #pragma unroll
        for (int nj = 0; nj < 8; nj++) {
            s[nj][0] = __expf(s[nj][0] - mn0);
            s[nj][1] = __expf(s[nj][1] - mn0);
            s[nj][2] = __expf(s[nj][2] - mn1);
            s[nj][3] = __expf(s[nj][3] - mn1);
            sum0 += s[nj][0] + s[nj][1];
            sum1 += s[nj][2] + s[nj][3];
        }
        sum0 += __shfl_xor_sync(0xffffffffu, sum0, 1);
        sum0 += __shfl_xor_sync(0xffffffffu, sum0, 2);
        sum1 += __shfl_xor_sync(0xffffffffu, sum1, 1);
        sum1 += __shfl_xor_sync(0xffffffffu, sum1, 2);
        lrow0 = lrow0 * c0 + sum0;
        lrow1 = lrow1 * c1 + sum1;
        #pragma unroll
        for (int nj = 0; nj < 8; nj++) {
            o[nj][0] *= c0; o[nj][1] *= c0;
            o[nj][2] *= c1; o[nj][3] *= c1;
        }
        mrow0 = mn0; mrow1 = mn1;

        #pragma unroll
        for (int ks = 0; ks < 4; ks++) {
            uint32_t a[4];
            a[0] = packf2h(s[2 * ks][0], s[2 * ks][1]);
            a[1] = packf2h(s[2 * ks][2], s[2 * ks][3]);
            a[2] = packf2h(s[2 * ks + 1][0], s[2 * ks + 1][1]);
            a[3] = packf2h(s[2 * ks + 1][2], s[2 * ks + 1][3]);
            #pragma unroll
            for (int np = 0; np < 4; np++) {
                const uint32_t addr = vb
                    + (ks * 16 + (lane & 7) + (lane & 8)) * FROWB
                    + (np * 16 + ((lane >> 4) & 1) * 8) * 2;
                uint32_t r0, r1, r2, r3;
                ldsm_x4t(addr, r0, r1, r2, r3);
                uint32_t b0[2] = {r0, r1}, b1[2] = {r2, r3};
                mma16816(o[np * 2], a, b0);
                mma16816(o[np * 2 + 1], a, b1);
            }
        }
        __syncthreads();
    }

    // epilogue: write fp16 y (input to projection GEMM)
    const float inv0 = 1.f / lrow0, inv1 = 1.f / lrow1;
    const int b = bh >> 4, h = bh & 15;
    const int row0 = qbase + wm + (lane >> 2);
    const size_t y0 = ((size_t)(b * Ss + row0)) * Dd + h * HDIM;
    const size_t y1 = y0 + (size_t)8 * Dd;
    #pragma unroll
    for (int nj = 0; nj < 8; nj++) {
        const int col = nj * 8 + 2 * (lane & 3);
        *(uint32_t*)(g_hA + y0 + col) = packf2h(o[nj][0] * inv0, o[nj][1] * inv0);
        *(uint32_t*)(g_hA + y1 + col) = packf2h(o[nj][2] * inv1, o[nj][3] * inv1);
    }
}

// ---------------------------------------------------------------------------
// Launch
// ---------------------------------------------------------------------------
extern "C" void kernel_launch(void* const* d_in, const int* in_sizes, int n_in,
                              void* d_out, int out_size) {
    const float* x      = (const float*)d_in[0];
    const float* norm_w = (const float*)d_in[1];
    const float* qkv_w  = (const float*)d_in[2];
    const float* qkv_b  = (const float*)d_in[3];
    const float* proj_w = (const float*)d_in[4];
    const float* proj_b = (const float*)d_in[5];
    float* out = (float*)d_out;

    float* p_qkv;
    __half *p_hA, *p_hW;
    cudaGetSymbolAddress((void**)&p_qkv, g_qkv);
    cudaGetSymbolAddress((void**)&p_hA, g_hA);
    cudaGetSymbolAddress((void**)&p_hW, g_hW);

    cudaFuncSetAttribute(gemm_f16, cudaFuncAttributeMaxDynamicSharedMemorySize, GSMEM);

    // 1) fused RMSNorm + fp16 convert -> g_hA
    rmsnorm_h_kernel<<<Mrows, 256>>>(x, norm_w);
    // 2) RoPE table
    rope_table_kernel<<<Ss, 32>>>();
    // 3) weights -> fp16
    split_f16_hi_kernel<<<(QKVD * Dd / 4 + 255) / 256, 256>>>(
        (const float4*)qkv_w, (uint2*)p_hW, QKVD * Dd / 4);
    // 4) QKV GEMM (fp16 single-pass)
    gemm_f16<<<dim3(QKVD / 128, Mrows / 128), 256, GSMEM>>>(
        p_hA, p_hW, qkv_b, p_qkv, Mrows, QKVD, Dd);
    // 5) fused RoPE + fp16 convert + head-major transpose
    {
        const int total = Bb * Ss * Hh * 32;
        rope_cvt_kernel<<<(total + 255) / 256, 256>>>();
    }
    // 6) tensor-core flash attention (writes fp16 y into g_hA)
    flash_mma_kernel<<<dim3(Ss / 64, Bb * Hh), 128>>>();
    // 7) proj weights -> fp16
    split_f16_hi_kernel<<<(Dd * Dd / 4 + 255) / 256, 256>>>(
        (const float4*)proj_w, (uint2*)p_hW, Dd * Dd / 4);
    // 8) Output projection (fp16 single-pass)
    gemm_f16<<<dim3(Dd / 128, Mrows / 128), 256, GSMEM>>>(
        p_hA, p_hW, proj_b, out, Mrows, Dd, Dd);

    (void)in_sizes; (void)n_in; (void)out_size;
}

// round 10
// speedup vs baseline: 7.5005x; 1.0469x over previous
#include <cuda_runtime.h>
#include <cuda_fp16.h>
#include <cstdint>
#include <math.h>

#define Bb 2
#define Ss 2048
#define Dd 1024
#define Hh 16
#define HDIM 64
#define Mrows (Bb*Ss)   // 4096
#define QKVD (3*Dd)     // 3072

// ---------------------------------------------------------------------------
// Scratch
// ---------------------------------------------------------------------------
__device__ float g_cos[Ss * 32];
__device__ float g_sin[Ss * 32];
__device__ __half g_hA[(size_t)Mrows * Dd];
__device__ __half g_hW[(size_t)QKVD * Dd];
// head-major fp16 q/k/v for attention: [b*16+h][s][64]
__device__ __half g_qh[(size_t)Bb * Hh * Ss * HDIM];
__device__ __half g_kh[(size_t)Bb * Hh * Ss * HDIM];
__device__ __half g_vh[(size_t)Bb * Hh * Ss * HDIM];

// ---------------------------------------------------------------------------
// Helpers
// ---------------------------------------------------------------------------
__device__ __forceinline__ uint32_t smem_to_u32(const void* p) {
    uint32_t a;
    asm("{ .reg .u64 t; cvta.to.shared.u64 t, %1; cvt.u32.u64 %0, t; }"
        : "=r"(a) : "l"(p));
    return a;
}
__device__ __forceinline__ void ldsm_x4(uint32_t addr, uint32_t& r0, uint32_t& r1,
                                        uint32_t& r2, uint32_t& r3) {
    asm volatile("ldmatrix.sync.aligned.m8n8.x4.shared.b16 {%0,%1,%2,%3}, [%4];"
                 : "=r"(r0), "=r"(r1), "=r"(r2), "=r"(r3) : "r"(addr));
}
__device__ __forceinline__ void ldsm_x4t(uint32_t addr, uint32_t& r0, uint32_t& r1,
                                         uint32_t& r2, uint32_t& r3) {
    asm volatile("ldmatrix.sync.aligned.m8n8.x4.trans.shared.b16 {%0,%1,%2,%3}, [%4];"
                 : "=r"(r0), "=r"(r1), "=r"(r2), "=r"(r3) : "r"(addr));
}
__device__ __forceinline__ void mma16816(float* c, const uint32_t* a, const uint32_t* b) {
    asm volatile("mma.sync.aligned.m16n8k16.row.col.f32.f16.f16.f32 "
                 "{%0,%1,%2,%3}, {%4,%5,%6,%7}, {%8,%9}, {%0,%1,%2,%3};"
                 : "+f"(c[0]), "+f"(c[1]), "+f"(c[2]), "+f"(c[3])
                 : "r"(a[0]), "r"(a[1]), "r"(a[2]), "r"(a[3]), "r"(b[0]), "r"(b[1]));
}
#define CP_ASYNC16(sa, ga) \
    asm volatile("cp.async.cg.shared.global [%0], [%1], 16;" :: "r"(sa), "l"(ga))
#define CP_COMMIT() asm volatile("cp.async.commit_group;" ::: "memory")
#define CP_WAIT1()  asm volatile("cp.async.wait_group 1;" ::: "memory")
#define CP_WAIT0()  asm volatile("cp.async.wait_group 0;" ::: "memory")

__device__ __forceinline__ uint32_t packf2h(float a, float b) {
    __half2 h = __floats2half2_rn(a, b);
    return *(uint32_t*)&h;
}
__device__ __forceinline__ uint32_t packh(__half a, __half b) {
    return ((uint32_t)__half_as_ushort(b) << 16) | (uint32_t)__half_as_ushort(a);
}

// ---------------------------------------------------------------------------
// Fused RMSNorm + fp16 convert: x -> g_hA
// ---------------------------------------------------------------------------
__global__ void __launch_bounds__(256)
rmsnorm_h_kernel(const float* __restrict__ x, const float* __restrict__ w) {
    const int row = blockIdx.x;
    const float4* xr = (const float4*)(x + (size_t)row * Dd);
    const float4 v = xr[threadIdx.x];
    float ss = v.x * v.x + v.y * v.y + v.z * v.z + v.w * v.w;
    __shared__ float red[8];
    #pragma unroll
    for (int o = 16; o > 0; o >>= 1) ss += __shfl_xor_sync(0xffffffffu, ss, o);
    const int wid = threadIdx.x >> 5, lid = threadIdx.x & 31;
    if (lid == 0) red[wid] = ss;
    __syncthreads();
    if (wid == 0) {
        ss = (lid < 8) ? red[lid] : 0.f;
        #pragma unroll
        for (int o = 4; o > 0; o >>= 1) ss += __shfl_xor_sync(0xffffffffu, ss, o);
        if (lid == 0) red[0] = ss;
    }
    __syncthreads();
    const float inv = rsqrtf(red[0] * (1.0f / Dd) + 1e-6f);
    const float4 wv = ((const float4*)w)[threadIdx.x];
    const size_t o4 = (size_t)row * (Dd / 4) + threadIdx.x;
    ((uint2*)g_hA)[o4] = make_uint2(
        packh(__float2half_rn(v.x * inv * wv.x), __float2half_rn(v.y * inv * wv.y)),
        packh(__float2half_rn(v.z * inv * wv.z), __float2half_rn(v.w * inv * wv.w)));
}

// ---------------------------------------------------------------------------
// RoPE table
// ---------------------------------------------------------------------------
__global__ void rope_table_kernel() {
    const int t = blockIdx.x;
    const int i = threadIdx.x;
    double inv = pow(10000.0, -((double)(2 * i)) / 64.0);
    double a = (double)t * inv;
    g_cos[t * 32 + i] = (float)cos(a);
    g_sin[t * 32 + i] = (float)sin(a);
}

// ---------------------------------------------------------------------------
// fp32 -> fp16 (weights)
// ---------------------------------------------------------------------------
__global__ void split_f16_hi_kernel(const float4* __restrict__ src,
                                    uint2* __restrict__ hi, int n4) {
    int i = blockIdx.x * blockDim.x + threadIdx.x;
    if (i >= n4) return;
    float4 v = src[i];
    hi[i] = make_uint2(packh(__float2half_rn(v.x), __float2half_rn(v.y)),
                       packh(__float2half_rn(v.z), __float2half_rn(v.w)));
}

// ---------------------------------------------------------------------------
// Single-pass fp16 GEMM via mma.sync: C = A * W^T + bias
//   mode 0: write fp32 C (+bias)
//   mode 1: QKV epilogue — add bias, apply RoPE (q,k) / passthrough (v),
//           scale q by 0.125, write fp16 head-major into g_qh/g_kh/g_vh.
//   Each warp's 64-col span aligns exactly with one head; the RoPE pair
//   (j, j+32) is (acc[mi][nj], acc[mi][nj+4]) in the SAME thread.
// ---------------------------------------------------------------------------
#define PADB  80
#define TILEB (128 * PADB)           // 10240
#define STAGEB (2 * TILEB)           // 20480: A, W
#define NSTAGE 3
#define GSMEM (NSTAGE * STAGEB)      // 61440

__global__ void __launch_bounds__(256)
gemm_f16(const __half* __restrict__ Ahi, const __half* __restrict__ Whi,
         const float* __restrict__ bias, float* __restrict__ C,
         int M, int N, int K, int mode) {
    extern __shared__ char smem[];
    const uint32_t sb = smem_to_u32(smem);
    const int tid = threadIdx.x, lane = tid & 31, w = tid >> 5;
    const int bm = blockIdx.y * 128, bn = blockIdx.x * 128;
    const int wm = (w >> 1) * 32, wn = (w & 1) * 64;

    auto load_stage = [&](int s, int k0) {
        const uint32_t st = sb + s * STAGEB;
        #pragma unroll
        for (int t = 0; t < 2; t++) {
            const __half* src = (t == 0 ? Ahi : Whi)
                                + (size_t)(t == 0 ? bm : bn) * K + k0;
            const uint32_t tb = st + t * TILEB;
            #pragma unroll
            for (int j = 0; j < 2; j++) {
                const int c = tid + j * 256;
                const int row = c >> 2, c16 = c & 3;
                const uint32_t sa = tb + row * PADB + c16 * 16;
                const __half* ga = src + (size_t)row * K + c16 * 8;
                CP_ASYNC16(sa, ga);
            }
        }
    };

    float acc[2][8][4];
    #pragma unroll
    for (int mi = 0; mi < 2; mi++)
        #pragma unroll
        for (int nj = 0; nj < 8; nj++)
            #pragma unroll
            for (int r = 0; r < 4; r++) acc[mi][nj][r] = 0.f;

    load_stage(0, 0);  CP_COMMIT();
    load_stage(1, 32); CP_COMMIT();

    const int nch = K >> 5;
    const int sel = lane >> 3;
    const int asub = (sel & 1) * 8, ak8 = (sel >> 1) * 8;
    const int nsub = (sel >> 1) * 8, bk8 = (sel & 1) * 8;

    for (int cidx = 0; cidx < nch; cidx++) {
        CP_WAIT1();
        __syncthreads();
        if (cidx + 2 < nch) load_stage((cidx + 2) % NSTAGE, (cidx + 2) * 32);
        CP_COMMIT();

        const uint32_t st = sb + (cidx % NSTAGE) * STAGEB;
        #pragma unroll
        for (int kk = 0; kk < 2; kk++) {
            const int ko = kk * 16;
            uint32_t ah[2][4], wh[8][2];
            #pragma unroll
            for (int mi = 0; mi < 2; mi++) {
                const uint32_t addr = st + (wm + mi * 16 + (lane & 7) + asub) * PADB
                                      + (ko + ak8) * 2;
                ldsm_x4(addr, ah[mi][0], ah[mi][1], ah[mi][2], ah[mi][3]);
            }
            #pragma unroll
            for (int ni = 0; ni < 4; ni++) {
                const uint32_t addr = st + TILEB
                                      + (wn + ni * 16 + (lane & 7) + nsub) * PADB
                                      + (ko + bk8) * 2;
                uint32_t r0, r1, r2, r3;
                ldsm_x4(addr, r0, r1, r2, r3);
                wh[ni * 2][0] = r0; wh[ni * 2][1] = r1;
                wh[ni * 2 + 1][0] = r2; wh[ni * 2 + 1][1] = r3;
            }
            #pragma unroll
            for (int mi = 0; mi < 2; mi++)
                #pragma unroll
                for (int nj = 0; nj < 8; nj++)
                    mma16816(acc[mi][nj], ah[mi], wh[nj]);
        }
    }

    if (mode == 0) {
        #pragma unroll
        for (int mi = 0; mi < 2; mi++) {
            const int row = bm + wm + mi * 16 + (lane >> 2);
            #pragma unroll
            for (int nj = 0; nj < 8; nj++) {
                const int col = bn + wn + nj * 8 + (lane & 3) * 2;
                const float b0 = bias[col], b1 = bias[col + 1];
                float2* c0 = (float2*)(C + (size_t)row * N + col);
                float2* c1 = (float2*)(C + (size_t)(row + 8) * N + col);
                *c0 = make_float2(acc[mi][nj][0] + b0, acc[mi][nj][1] + b1);
                *c1 = make_float2(acc[mi][nj][2] + b0, acc[mi][nj][3] + b1);
            }
        }
    } else {
        // QKV epilogue: bias + RoPE + fp16 head-major store
        const int gc = bn + wn;                 // warp col base (multiple of 64)
        const int type = gc >> 10;              // 0=q, 1=k, 2=v
        const int hh = (gc & 1023) >> 6;        // head index
        __half* dstbase = (type == 0) ? g_qh : (type == 1 ? g_kh : g_vh);
        const float qs = (type == 0) ? 0.125f : 1.0f;
        #pragma unroll
        for (int mi = 0; mi < 2; mi++) {
            const int row = bm + wm + mi * 16 + (lane >> 2);
            #pragma unroll
            for (int rr = 0; rr < 2; rr++) {
                const int r = row + rr * 8;
                const int s = r & (Ss - 1);
                const int bidx = r >> 11;
                __half* dst = dstbase + ((size_t)(bidx * Hh + hh) * Ss + s) * HDIM;
                const int ci = rr * 2;
                #pragma unroll
                for (int nj = 0; nj < 4; nj++) {
                    const int j = nj * 8 + 2 * (lane & 3);
                    const float a0 = acc[mi][nj][ci]         + bias[gc + j];
                    const float a1 = acc[mi][nj][ci + 1]     + bias[gc + j + 1];
                    const float b0 = acc[mi][nj + 4][ci]     + bias[gc + j + 32];
                    const float b1 = acc[mi][nj + 4][ci + 1] + bias[gc + j + 33];
                    float o0, o1, o2, o3;
                    if (type == 2) {
                        o0 = a0; o1 = a1; o2 = b0; o3 = b1;
                    } else {
                        const float2 cc = *(const float2*)&g_cos[s * 32 + j];
                        const float2 sn = *(const float2*)&g_sin[s * 32 + j];
                        o0 = (a0 * cc.x - b0 * sn.x) * qs;
                        o1 = (a1 * cc.y - b1 * sn.y) * qs;
                        o2 = (b0 * cc.x + a0 * sn.x) * qs;
                        o3 = (b1 * cc.y + a1 * sn.y) * qs;
                    }
                    *(uint32_t*)(dst + j)      = packf2h(o0, o1);
                    *(uint32_t*)(dst + j + 32) = packf2h(o2, o3);
                }
            }
        }
    }
}

// ---------------------------------------------------------------------------
// Tensor-core flash attention (causal). Epilogue writes fp16 y into g_hA.
// ---------------------------------------------------------------------------
#define FROWH 72
#define FROWB (FROWH * 2)
#define FTILE (64 * FROWB)

__global__ void __launch_bounds__(128)
flash_mma_kernel() {
    __shared__ __align__(16) char fsm[5 * FTILE];   // Q | K0 | K1 | V0 | V1
    const int qblk = gridDim.x - 1 - blockIdx.x;    // long CTAs first
    const int bh = blockIdx.y;
    const int tid = threadIdx.x, lane = tid & 31, w = tid >> 5;
    const int qbase = qblk * 64, wm = w * 16;
    const uint32_t sq = smem_to_u32(fsm);
    const uint32_t sk0 = sq + FTILE, sk1 = sq + 2 * FTILE;
    const uint32_t sv0 = sq + 3 * FTILE, sv1 = sq + 4 * FTILE;

    const size_t hb = (size_t)bh * Ss * HDIM;

    {
        const __half* qsrc = g_qh + hb + (size_t)qbase * HDIM;
        #pragma unroll
        for (int i = 0; i < 4; i++) {
            const int c = tid + i * 128;
            const int row = c >> 3, col = (c & 7) * 8;
            CP_ASYNC16(sq + row * FROWB + col * 2, qsrc + row * HDIM + col);
        }
    }
    auto fetch_kv = [&](int kt) {
        const __half* ksrc = g_kh + hb + (size_t)(kt * 64) * HDIM;
        const __half* vsrc = g_vh + hb + (size_t)(kt * 64) * HDIM;
        const uint32_t kb = (kt & 1) ? sk1 : sk0;
        const uint32_t vb = (kt & 1) ? sv1 : sv0;
        #pragma unroll
        for (int i = 0; i < 4; i++) {
            const int c = tid + i * 128;
            const int row = c >> 3, col = (c & 7) * 8;
            CP_ASYNC16(kb + row * FROWB + col * 2, ksrc + row * HDIM + col);
            CP_ASYNC16(vb + row * FROWB + col * 2, vsrc + row * HDIM + col);
        }
    };
    const int nt = qblk + 1;
    fetch_kv(0); CP_COMMIT();
    if (nt > 1) { fetch_kv(1); CP_COMMIT(); }

    uint32_t qf[4][4];
    float o[8][4];
    #pragma unroll
    for (int nj = 0; nj < 8; nj++)
        #pragma unroll
        for (int r = 0; r < 4; r++) o[nj][r] = 0.f;
    float mrow0 = -INFINITY, mrow1 = -INFINITY, lrow0 = 0.f, lrow1 = 0.f;

    for (int kt = 0; kt < nt; kt++) {
        if (kt + 1 < nt) {
            if (kt) { fetch_kv(kt + 1); CP_COMMIT(); }
            CP_WAIT1();
        } else {
            CP_WAIT0();
        }
        __syncthreads();

        if (kt == 0) {
            #pragma unroll
            for (int ks = 0; ks < 4; ks++) {
                const uint32_t addr = sq + (wm + (lane & 15)) * FROWB
                                      + (ks * 16 + (lane >> 4) * 8) * 2;
                ldsm_x4(addr, qf[ks][0], qf[ks][1], qf[ks][2], qf[ks][3]);
            }
        }

        const uint32_t kb = (kt & 1) ? sk1 : sk0;
        const uint32_t vb = (kt & 1) ? sv1 : sv0;

        float s[8][4];
        #pragma unroll
        for (int nj = 0; nj < 8; nj++)
            #pragma unroll
            for (int r = 0; r < 4; r++) s[nj][r] = 0.f;
        const int sel = lane >> 3;
        #pragma unroll
        for (int ks = 0; ks < 4; ks++) {
            #pragma unroll
            for (int np = 0; np < 4; np++) {
                const uint32_t addr = kb
                    + (np * 16 + (lane & 7) + (sel >> 1) * 8) * FROWB
                    + (ks * 16 + (sel & 1) * 8) * 2;
                uint32_t r0, r1, r2, r3;
                ldsm_x4(addr, r0, r1, r2, r3);
                uint32_t b0[2] = {r0, r1}, b1[2] = {r2, r3};
                mma16816(s[np * 2], qf[ks], b0);
                mma16816(s[np * 2 + 1], qf[ks], b1);
            }
        }

        if (kt == qblk) {
            const int lr0 = wm + (lane >> 2), lr1 = lr0 + 8;
            #pragma unroll
            for (int nj = 0; nj < 8; nj++) {
                const int ck = nj * 8 + 2 * (lane & 3);
                if (ck > lr0)     s[nj][0] = -INFINITY;
                if (ck + 1 > lr0) s[nj][1] = -INFINITY;
                if (ck > lr1)     s[nj][2] = -INFINITY;
                if (ck + 1 > lr1) s[nj][3] = -INFINITY;
            }
        }

        float mx0 = -INFINITY, mx1 = -INFINITY;
        #pragma unroll
        for (int nj = 0; nj < 8; nj++) {
            mx0 = fmaxf(mx0, fmaxf(s[nj][0], s[nj][1]));
            mx1 = fmaxf(mx1, fmaxf(s[nj][2], s[nj][3]));
        }
        mx0 = fmaxf(mx0, __shfl_xor_sync(0xffffffffu, mx0, 1));
        mx0 = fmaxf(mx0, __shfl_xor_sync(0xffffffffu, mx0, 2));
        mx1 = fmaxf(mx1, __shfl_xor_sync(0xffffffffu, mx1, 1));
        mx1 = fmaxf(mx1, __shfl_xor_sync(0xffffffffu, mx1, 2));
        const float mn0 = fmaxf(mrow0, mx0), mn1 = fmaxf(mrow1, mx1);
        const float c0 = __expf(mrow0 - mn0), c1 = __expf(mrow1 - mn1);
        float sum0 = 0.f, sum1 = 0.f;
        #pragma unroll
        for (int nj = 0; nj < 8; nj++) {
            s[nj][0] = __expf(s[nj][0] - mn0);
            s[nj][1] = __expf(s[nj][1] - mn0);
            s[nj][2] = __expf(s[nj][2] - mn1);
            s[nj][3] = __expf(s[nj][3] - mn1);
            sum0 += s[nj][0] + s[nj][1];
            sum1 += s[nj][2] + s[nj][3];
        }
        sum0 += __shfl_xor_sync(0xffffffffu, sum0, 1);
        sum0 += __shfl_xor_sync(0xffffffffu, sum0, 2);
        sum1 += __shfl_xor_sync(0xffffffffu, sum1, 1);
        sum1 += __shfl_xor_sync(0xffffffffu, sum1, 2);
        lrow0 = lrow0 * c0 + sum0;
        lrow1 = lrow1 * c1 + sum1;
        #pragma unroll
        for (int nj = 0; nj < 8; nj++) {
            o[nj][0] *= c0; o[nj][1] *= c0;
            o[nj][2] *= c1; o[nj][3] *= c1;
        }
        mrow0 = mn0; mrow1 = mn1;

        #pragma unroll
        for (int ks = 0; ks < 4; ks++) {
            uint32_t a[4];
            a[0] = packf2h(s[2 * ks][0], s[2 * ks][1]);
            a[1] = packf2h(s[2 * ks][2], s[2 * ks][3]);
            a[2] = packf2h(s[2 * ks + 1][0], s[2 * ks + 1][1]);
            a[3] = packf2h(s[2 * ks + 1][2], s[2 * ks + 1][3]);
            #pragma unroll
            for (int np = 0; np < 4; np++) {
                const uint32_t addr = vb
                    + (ks * 16 + (lane & 7) + (lane & 8)) * FROWB
                    + (np * 16 + ((lane >> 4) & 1) * 8) * 2;
                uint32_t r0, r1, r2, r3;
                ldsm_x4t(addr, r0, r1, r2, r3);
                uint32_t b0[2] = {r0, r1}, b1[2] = {r2, r3};
                mma16816(o[np * 2], a, b0);
                mma16816(o[np * 2 + 1], a, b1);
            }
        }
        __syncthreads();
    }

    // epilogue: write fp16 y (input to projection GEMM)
    const float inv0 = 1.f / lrow0, inv1 = 1.f / lrow1;
    const int b = bh >> 4, h = bh & 15;
    const int row0 = qbase + wm + (lane >> 2);
    const size_t y0 = ((size_t)(b * Ss + row0)) * Dd + h * HDIM;
    const size_t y1 = y0 + (size_t)8 * Dd;
    #pragma unroll
    for (int nj = 0; nj < 8; nj++) {
        const int col = nj * 8 + 2 * (lane & 3);
        *(uint32_t*)(g_hA + y0 + col) = packf2h(o[nj][0] * inv0, o[nj][1] * inv0);
        *(uint32_t*)(g_hA + y1 + col) = packf2h(o[nj][2] * inv1, o[nj][3] * inv1);
    }
}

// ---------------------------------------------------------------------------
// Launch
// ---------------------------------------------------------------------------
extern "C" void kernel_launch(void* const* d_in, const int* in_sizes, int n_in,
                              void* d_out, int out_size) {
    const float* x      = (const float*)d_in[0];
    const float* norm_w = (const float*)d_in[1];
    const float* qkv_w  = (const float*)d_in[2];
    const float* qkv_b  = (const float*)d_in[3];
    const float* proj_w = (const float*)d_in[4];
    const float* proj_b = (const float*)d_in[5];
    float* out = (float*)d_out;

    __half *p_hA, *p_hW;
    cudaGetSymbolAddress((void**)&p_hA, g_hA);
    cudaGetSymbolAddress((void**)&p_hW, g_hW);

    cudaFuncSetAttribute(gemm_f16, cudaFuncAttributeMaxDynamicSharedMemorySize, GSMEM);

    // 1) fused RMSNorm + fp16 convert -> g_hA
    rmsnorm_h_kernel<<<Mrows, 256>>>(x, norm_w);
    // 2) RoPE table
    rope_table_kernel<<<Ss, 32>>>();
    // 3) weights -> fp16
    split_f16_hi_kernel<<<(QKVD * Dd / 4 + 255) / 256, 256>>>(
        (const float4*)qkv_w, (uint2*)p_hW, QKVD * Dd / 4);
    // 4) QKV GEMM with fused bias+RoPE+fp16 head-major epilogue
    gemm_f16<<<dim3(QKVD / 128, Mrows / 128), 256, GSMEM>>>(
        p_hA, p_hW, qkv_b, out /*unused*/, Mrows, QKVD, Dd, 1);
    // 5) tensor-core flash attention (writes fp16 y into g_hA)
    flash_mma_kernel<<<dim3(Ss / 64, Bb * Hh), 128>>>();
    // 6) proj weights -> fp16
    split_f16_hi_kernel<<<(Dd * Dd / 4 + 255) / 256, 256>>>(
        (const float4*)proj_w, (uint2*)p_hW, Dd * Dd / 4);
    // 7) Output projection (plain fp32 epilogue)
    gemm_f16<<<dim3(Dd / 128, Mrows / 128), 256, GSMEM>>>(
        p_hA, p_hW, proj_b, out, Mrows, Dd, Dd, 0);

    (void)in_sizes; (void)n_in; (void)out_size;
}